// round 13
// baseline (speedup 1.0000x reference)
#include <cuda_runtime.h>
#include <cuda_fp16.h>

#define NN   20000
#define EE   640000
#define HH   128
#define MT   128            // edges per tile (MMA M)
#define ETHR 512            // edge kernel threads (16 warps, 16x64 warp-tiles)
#define NTILES (EE / MT)    // 5000

#define NTILE 64            // node kernel tile
#define NPAD  132
#define NTHR  256

typedef unsigned int u32;
typedef unsigned long long u64;

// Padded fp16 row length (136*2=272B -> ldmatrix conflict-free phases)
#define KP   136
#define IMG  (128 * KP)            // one [128][136] fp16 image (elements)
#define STAGE_BYTES (IMG * 2)      // 34816 B per weight stage

// ---------------- device scratch (allocation-free rule) ----------------
__device__ __align__(16) float g_m_i[NN * HH];
__device__ __align__(16) float g_xupd[NN * 3];
__device__ int g_is64;
__device__ u32 g_ticket;
// 4 weight stages (W1a, W1b, W2, W3), each one [128][136] fp16 image [n][k]
__device__ __align__(16) __half g_wb[4 * IMG];

__device__ __forceinline__ float silu_f(float v) {
    return v * (1.0f / (1.0f + __expf(-v)));
}

// ---------------- mma.sync helpers (baseline ISA) ----------------
__device__ __forceinline__ u32 smem_u32(const void* p) {
    u32 a;
    asm("{ .reg .u64 t; cvta.to.shared.u64 t, %1; cvt.u32.u64 %0, t; }"
        : "=r"(a) : "l"(p));
    return a;
}
__device__ __forceinline__ void ldm4(u32* r, u32 addr) {
    asm volatile("ldmatrix.sync.aligned.m8n8.x4.shared.b16 {%0,%1,%2,%3}, [%4];"
                 : "=r"(r[0]), "=r"(r[1]), "=r"(r[2]), "=r"(r[3]) : "r"(addr));
}
__device__ __forceinline__ void mma_f16(float* c, const u32* a, u32 b0, u32 b1) {
    asm volatile(
        "mma.sync.aligned.m16n8k16.row.col.f32.f16.f16.f32 "
        "{%0,%1,%2,%3}, {%4,%5,%6,%7}, {%8,%9}, {%0,%1,%2,%3};"
        : "+f"(c[0]), "+f"(c[1]), "+f"(c[2]), "+f"(c[3])
        : "r"(a[0]), "r"(a[1]), "r"(a[2]), "r"(a[3]), "r"(b0), "r"(b1));
}
// store (a,b) as half2 into an activation image
__device__ __forceinline__ void store_act(char* A, int m, int n, float a, float b) {
    __half2 p = __floats2half2_rn(a, b);
    *(u32*)(A + (u32)(m * KP + n) * 2) = *(u32*)&p;
}
// vector fp32x2 reduction to global (sm_90+ baseline PTX)
__device__ __forceinline__ void red2_global(float* p, float a, float b) {
    asm volatile("red.global.add.v2.f32 [%0], {%1, %2};"
                 :: "l"(p), "f"(a), "f"(b) : "memory");
}

// cp.async weight staging: one 34816B stage image -> smem, one commit group
__device__ __forceinline__ void stage_w(u32 dst, const __half* src, int tid) {
    const char* g = (const char*)src;
#pragma unroll
    for (int i = 0; i < 5; i++) {
        int idx = tid + i * ETHR;           // need 0..2175
        if (idx < 2176)
            asm volatile("cp.async.cg.shared.global [%0], [%1], 16;"
                         :: "r"(dst + idx * 16), "l"(g + (size_t)idx * 16) : "memory");
    }
    asm volatile("cp.async.commit_group;" ::: "memory");
}
template <int N> __device__ __forceinline__ void cp_wait() {
    asm volatile("cp.async.wait_group %0;" :: "n"(N) : "memory");
}

// ---------------------------------------------------------------------------
// Kernel 0: zero accumulators + ticket, detect index width, bake fp16 weight
// images [n][k] padded to KP (B^T, k contiguous) for ldmatrix.
// ---------------------------------------------------------------------------
__global__ void prep_kernel(const void* ei, const float* ew1,
                            const float* ew2, const float* cw1) {
    int i = blockIdx.x * blockDim.x + threadIdx.x;
    const int total = NN * HH + NN * 3;
    if (i < total) {
        if (i < NN * HH) g_m_i[i] = 0.0f;
        else             g_xupd[i - NN * HH] = 0.0f;
    }
    if (i < 65536) {
        int s = i >> 14, r = i & 16383;
        int k = r >> 7, n = r & 127;
        float v;
        if      (s == 0) v = ew1[k * 128 + n];
        else if (s == 1) v = ew1[(128 + k) * 128 + n];
        else if (s == 2) v = ew2[k * 128 + n];
        else             v = cw1[k * 128 + n];
        g_wb[(size_t)s * IMG + n * KP + k] = __float2half_rn(v);
    }
    if (blockIdx.x == 0 && threadIdx.x == 0) {
        g_ticket = 0u;
        const unsigned* w = (const unsigned*)ei;
        int is64 = 1;
        for (int kk = 0; kk < 32; kk++)
            if (w[2 * kk + 1] != 0u) { is64 = 0; break; }
        g_is64 = is64;
    }
}

// SMEM byte offsets (edge kernel): 4 resident weight stages + 2 A images + misc
#define OFF_W(s) ((s) * STAGE_BYTES)         // 0 .. 139264
#define OFF_A1   (4 * STAGE_BYTES)           // 139264
#define OFF_A2   (OFF_A1 + IMG * 2)          // 174080
#define OFF_MISC (OFF_A2 + IMG * 2)          // 208896
#define SMEM_EDGE (OFF_MISC + 6720)          // 215616

// One K=128 GEMM: warp-tile 16 rows x 64 cols, pure fp16.
// acc[8][4], acc[2t,2t+1] cover cols n = nh*64 + t*16 .. +15.
__device__ __forceinline__ void gemm_mma(float acc[8][4],
                                         u32 aImg, u32 wB,
                                         int lane, int wm, int nh)
{
    const int rowA = wm * 16 + (lane & 15);
    const u32 aoff = (u32)(rowA * KP + ((lane & 16) ? 8 : 0)) * 2;
    const int rowB = nh * 64 + ((lane & 16) ? 8 : 0) + (lane & 7);
    const u32 boff = (u32)(rowB * KP + ((lane & 8) ? 8 : 0)) * 2;

#pragma unroll
    for (int k0 = 0; k0 < 8; k0++) {
        u32 ah[4];
        ldm4(ah, aImg + aoff + k0 * 32);
#pragma unroll
        for (int t = 0; t < 4; t++) {
            u32 bh[4];
            ldm4(bh, wB + boff + (u32)t * (16 * KP * 2) + k0 * 32);
            mma_f16(acc[2 * t],     ah, bh[0], bh[1]);
            mma_f16(acc[2 * t + 1], ah, bh[2], bh[3]);
        }
    }
}

// ---------------------------------------------------------------------------
// Kernel 1: persistent fused edge pipeline (fp16 mma.sync, ticket queue)
// ---------------------------------------------------------------------------
__global__ void __launch_bounds__(ETHR, 1) edge_kernel(
    const float* __restrict__ h, const float* __restrict__ x,
    const void* __restrict__ ei,
    const float* __restrict__ ew1,   // radial-row weights (fp32)
    const float* __restrict__ eb1, const float* __restrict__ eb2,
    const float* __restrict__ cb1, const float* __restrict__ cw2)
{
    extern __shared__ char smem[];
    char*  A1 = smem + OFF_A1;
    char*  A2 = smem + OFF_A2;
    float* s_eb1 = (float*)(smem + OFF_MISC);
    float* s_eb2 = s_eb1 + 128;
    float* s_cb1 = s_eb2 + 128;
    float* s_wl  = s_cb1 + 128;
    float* s_cw2 = s_wl + 128;
    float* s_rad = s_cw2 + 128;
    float* s_cd  = s_rad + 128;          // [128][3]
    float* s_part = s_cd + 384;          // [128][2]
    int*   s_row = (int*)(s_part + 256);
    int*   s_col = s_row + 128;
    volatile u32* s_tile = (volatile u32*)(s_col + 128);

    const int tid  = threadIdx.x;
    const int lane = tid & 31;
    const int warp = tid >> 5;
    const int wm   = warp >> 1;          // 8 row groups of 16
    const int nh   = warp & 1;           // column half (64 cols)

    const u32 sb  = smem_u32(smem);
    const u32 a1A = sb + OFF_A1, a2A = sb + OFF_A2;

    // ---- one-time prologue: all 4 weight stages + constants ----
    stage_w(sb + OFF_W(0), g_wb,           tid);
    stage_w(sb + OFF_W(1), g_wb + IMG,     tid);
    stage_w(sb + OFF_W(2), g_wb + 2 * IMG, tid);
    stage_w(sb + OFF_W(3), g_wb + 3 * IMG, tid);
    if (tid < 128) {
        s_eb1[tid] = eb1[tid];
        s_eb2[tid] = eb2[tid];
        s_cb1[tid] = cb1[tid];
        s_wl[tid]  = ew1[256 * 128 + tid];
        s_cw2[tid] = cw2[tid];
    }
    const int is64 = g_is64;
    cp_wait<0>();
    __syncthreads();

    const int l4 = lane >> 2, l2 = lane & 3;
    const int m0 = wm * 16 + l4, m1 = m0 + 8;
    const int gr = tid >> 2, gq = (tid & 3) * 32;   // gather row / col-quarter

    for (;;) {
        // ---- grab a tile ----
        if (tid == 0) *s_tile = atomicAdd(&g_ticket, 1u);
        __syncthreads();
        const u32 t = *s_tile;
        if (t >= NTILES) break;
        const int e0 = (int)t * MT;

        // ---- metadata ----
        if (tid < MT) {
            int e = e0 + tid;
            int r, c;
            if (is64) {
                const long long* p = (const long long*)ei;
                r = (int)p[e]; c = (int)p[EE + e];
            } else {
                const int* p = (const int*)ei;
                r = p[e]; c = p[EE + e];
            }
            s_row[tid] = r; s_col[tid] = c;
            float dx = x[r * 3 + 0] - x[c * 3 + 0];
            float dy = x[r * 3 + 1] - x[c * 3 + 1];
            float dz = x[r * 3 + 2] - x[c * 3 + 2];
            s_cd[tid * 3 + 0] = dx; s_cd[tid * 3 + 1] = dy; s_cd[tid * 3 + 2] = dz;
            s_rad[tid] = dx * dx + dy * dy + dz * dz;
        }
        __syncthreads();

        float acc[8][4];
#pragma unroll
        for (int tt = 0; tt < 8; tt++)
#pragma unroll
            for (int j = 0; j < 4; j++) acc[tt][j] = 0.0f;

        // ---- gather h[row]->A1 and h[col]->A2 (overlapped LDG bursts) ----
        {
            const float4* hr = (const float4*)(h + (size_t)s_row[gr] * HH + gq);
            const float4* hc = (const float4*)(h + (size_t)s_col[gr] * HH + gq);
            float4 fr[8], fc[8];
#pragma unroll
            for (int i = 0; i < 8; i++) { fr[i] = hr[i]; fc[i] = hc[i]; }
#pragma unroll
            for (int i = 0; i < 8; i++) {
                int c = gq + i * 4;
                store_act(A1, gr, c,     fr[i].x, fr[i].y);
                store_act(A1, gr, c + 2, fr[i].z, fr[i].w);
                store_act(A2, gr, c,     fc[i].x, fc[i].y);
                store_act(A2, gr, c + 2, fc[i].z, fc[i].w);
            }
        }
        __syncthreads();

        // ---- G1: both K-halves back-to-back (A1, A2 both ready) ----
        gemm_mma(acc, a1A, sb + OFF_W(0), lane, wm, nh);
        gemm_mma(acc, a2A, sb + OFF_W(1), lane, wm, nh);
        __syncthreads();

        // ---- epi1: t1 = silu(acc + eb1 + rad*wl) -> A1 ----
        {
            float r0 = s_rad[m0], r1 = s_rad[m1];
#pragma unroll
            for (int nt = 0; nt < 8; nt++) {
                float* a = acc[nt];
                int n = nh * 64 + nt * 8 + 2 * l2;
                float b0 = s_eb1[n], b1 = s_eb1[n + 1];
                float w0 = s_wl[n],  w1 = s_wl[n + 1];
                float v00 = silu_f(a[0] + b0 + r0 * w0);
                float v01 = silu_f(a[1] + b1 + r0 * w1);
                float v10 = silu_f(a[2] + b0 + r1 * w0);
                float v11 = silu_f(a[3] + b1 + r1 * w1);
                store_act(A1, m0, n, v00, v01);
                store_act(A1, m1, n, v10, v11);
                a[0] = a[1] = a[2] = a[3] = 0.0f;
            }
        }
        __syncthreads();
        gemm_mma(acc, a1A, sb + OFF_W(2), lane, wm, nh);
        __syncthreads();

        // ---- epi2: m_ij = silu(acc + eb2); v2 atomics; -> A2 ----
        {
            float* ga = g_m_i + (size_t)s_row[m0] * HH;
            float* gb = g_m_i + (size_t)s_row[m1] * HH;
#pragma unroll
            for (int nt = 0; nt < 8; nt++) {
                float* a = acc[nt];
                int n = nh * 64 + nt * 8 + 2 * l2;
                float b0 = s_eb2[n], b1 = s_eb2[n + 1];
                float v00 = silu_f(a[0] + b0);
                float v01 = silu_f(a[1] + b1);
                float v10 = silu_f(a[2] + b0);
                float v11 = silu_f(a[3] + b1);
                red2_global(ga + n, v00, v01);
                red2_global(gb + n, v10, v11);
                store_act(A2, m0, n, v00, v01);
                store_act(A2, m1, n, v10, v11);
                a[0] = a[1] = a[2] = a[3] = 0.0f;
            }
        }
        __syncthreads();
        gemm_mma(acc, a2A, sb + OFF_W(3), lane, wm, nh);

        // ---- epi3: coord_weight = silu(acc + cb1) . cw2 ----
        {
            float p0 = 0.0f, p1 = 0.0f;
#pragma unroll
            for (int nt = 0; nt < 8; nt++) {
                float* a = acc[nt];
                int n = nh * 64 + nt * 8 + 2 * l2;
                float b0 = s_cb1[n], b1 = s_cb1[n + 1];
                float c0 = s_cw2[n], c1 = s_cw2[n + 1];
                p0 += silu_f(a[0] + b0) * c0 + silu_f(a[1] + b1) * c1;
                p1 += silu_f(a[2] + b0) * c0 + silu_f(a[3] + b1) * c1;
            }
            p0 += __shfl_xor_sync(0xffffffffu, p0, 1);
            p0 += __shfl_xor_sync(0xffffffffu, p0, 2);
            p1 += __shfl_xor_sync(0xffffffffu, p1, 1);
            p1 += __shfl_xor_sync(0xffffffffu, p1, 2);
            if (l2 == 0) {
                s_part[m0 * 2 + nh] = p0;
                s_part[m1 * 2 + nh] = p1;
            }
        }
        __syncthreads();

        if (tid < MT) {
            float w = s_part[tid * 2] + s_part[tid * 2 + 1];
            int r = s_row[tid];
            atomicAdd(&g_xupd[r * 3 + 0], s_cd[tid * 3 + 0] * w);
            atomicAdd(&g_xupd[r * 3 + 1], s_cd[tid * 3 + 1] * w);
            atomicAdd(&g_xupd[r * 3 + 2], s_cd[tid * 3 + 2] * w);
        }
        __syncthreads();    // protect s_row/s_cd/s_part before next tile
    }
}

// ---------------------------------------------------------------------------
// Kernel 2: node MLP + residual + x epilogue (SIMT f32x2 — small workload)
// ---------------------------------------------------------------------------
__device__ __forceinline__ void fma2(u64& d, u64 a, u64 b) {
    asm("fma.rn.f32x2 %0, %1, %2, %0;" : "+l"(d) : "l"(a), "l"(b));
}
__device__ __forceinline__ float red2(u64 v) {
    return __uint_as_float((unsigned)v) + __uint_as_float((unsigned)(v >> 32));
}

__device__ __forceinline__ void gemm2(u64 acc[4][8],
                                      const float* __restrict__ W,
                                      const float* __restrict__ Sin,
                                      float2* __restrict__ wbuf2,
                                      int tid, int r0, int c0)
{
#pragma unroll 1
    for (int k0 = 0; k0 < 128; k0 += 16) {
        __syncthreads();
#pragma unroll
        for (int t = 0; t < 4; t++) {
            int idx = tid + t * 256;
            int k2 = idx >> 7, j = idx & 127;
            wbuf2[idx] = make_float2(W[(k0 + 2 * k2) * HH + j],
                                     W[(k0 + 2 * k2 + 1) * HH + j]);
        }
        __syncthreads();
#pragma unroll
        for (int k2 = 0; k2 < 8; k2++) {
            u64 bb[8], aa[4];
#pragma unroll
            for (int m = 0; m < 8; m++)
                bb[m] = *(const u64*)&wbuf2[k2 * 128 + c0 + 16 * m];
#pragma unroll
            for (int i = 0; i < 4; i++)
                aa[i] = *(const u64*)&Sin[(r0 + i) * NPAD + k0 + 2 * k2];
#pragma unroll
            for (int i = 0; i < 4; i++)
#pragma unroll
                for (int m = 0; m < 8; m++)
                    fma2(acc[i][m], aa[i], bb[m]);
        }
    }
}

__global__ void __launch_bounds__(NTHR, 2) node_kernel(
    const float* __restrict__ h, const float* __restrict__ x,
    const float* __restrict__ nw1, const float* __restrict__ nb1,
    const float* __restrict__ nw2, const float* __restrict__ nb2,
    float* __restrict__ out)
{
    extern __shared__ float smemf[];
    float*  S_h   = smemf;
    float*  S_m   = S_h + NTILE * NPAD;
    float*  S_act = S_m + NTILE * NPAD;
    float2* wbuf2 = (float2*)(S_act + NTILE * NPAD);

    const int tid = threadIdx.x;
    const int n0  = blockIdx.x * NTILE;

    const float4* h4 = (const float4*)h;
    const float4* m4 = (const float4*)g_m_i;
    for (int i = tid; i < NTILE * 32; i += NTHR) {
        int rl = i >> 5, q = i & 31;
        int r = n0 + rl;
        float4 vh = make_float4(0.f, 0.f, 0.f, 0.f);
        float4 vm = vh;
        if (r < NN) { vh = h4[r * 32 + q]; vm = m4[r * 32 + q]; }
        *(float4*)&S_h[rl * NPAD + q * 4] = vh;
        *(float4*)&S_m[rl * NPAD + q * 4] = vm;
    }

    const int r0 = (tid >> 4) * 4;
    const int c0 = tid & 15;
    u64 acc[4][8];

#pragma unroll
    for (int m = 0; m < 8; m++) {
        float b = nb1[c0 + 16 * m];
#pragma unroll
        for (int i = 0; i < 4; i++) acc[i][m] = (u64)__float_as_uint(b);
    }
    gemm2(acc, nw1,            S_h, wbuf2, tid, r0, c0);
    gemm2(acc, nw1 + 128 * HH, S_m, wbuf2, tid, r0, c0);

#pragma unroll
    for (int i = 0; i < 4; i++)
#pragma unroll
        for (int m = 0; m < 8; m++)
            S_act[(r0 + i) * NPAD + c0 + 16 * m] = silu_f(red2(acc[i][m]));

#pragma unroll
    for (int m = 0; m < 8; m++) {
        float b = nb2[c0 + 16 * m];
#pragma unroll
        for (int i = 0; i < 4; i++) acc[i][m] = (u64)__float_as_uint(b);
    }
    gemm2(acc, nw2, S_act, wbuf2, tid, r0, c0);

#pragma unroll
    for (int i = 0; i < 4; i++) {
        int r = n0 + r0 + i;
        if (r < NN) {
#pragma unroll
            for (int m = 0; m < 8; m++)
                out[r * HH + c0 + 16 * m] =
                    S_h[(r0 + i) * NPAD + c0 + 16 * m] + red2(acc[i][m]);
        }
    }

    if (tid < NTILE) {
        int r = n0 + tid;
        if (r < NN) {
            const float inv = 1.0f / (float)(NN - 1);
            out[NN * HH + r * 3 + 0] = x[r * 3 + 0] + g_xupd[r * 3 + 0] * inv;
            out[NN * HH + r * 3 + 1] = x[r * 3 + 1] + g_xupd[r * 3 + 1] * inv;
            out[NN * HH + r * 3 + 2] = x[r * 3 + 2] + g_xupd[r * 3 + 2] * inv;
        }
    }
}

// ---------------------------------------------------------------------------

extern "C" void kernel_launch(void* const* d_in, const int* in_sizes, int n_in,
                              void* d_out, int out_size) {
    const float* h   = (const float*)d_in[0];
    const float* x   = (const float*)d_in[1];
    const void*  ei  = d_in[2];
    const float* ew1 = (const float*)d_in[3];
    const float* eb1 = (const float*)d_in[4];
    const float* ew2 = (const float*)d_in[5];
    const float* eb2 = (const float*)d_in[6];
    const float* nw1 = (const float*)d_in[7];
    const float* nb1 = (const float*)d_in[8];
    const float* nw2 = (const float*)d_in[9];
    const float* nb2 = (const float*)d_in[10];
    const float* cw1 = (const float*)d_in[11];
    const float* cb1 = (const float*)d_in[12];
    const float* cw2 = (const float*)d_in[13];
    float* out = (float*)d_out;

    const int smem_node = (3 * NTILE * NPAD) * 4 + 8 * HH * 8;

    cudaFuncSetAttribute(edge_kernel, cudaFuncAttributeMaxDynamicSharedMemorySize, SMEM_EDGE);
    cudaFuncSetAttribute(node_kernel, cudaFuncAttributeMaxDynamicSharedMemorySize, smem_node);

    int dev = 0, nsm = 148;
    cudaGetDevice(&dev);
    cudaDeviceGetAttribute(&nsm, cudaDevAttrMultiProcessorCount, dev);

    const int total = NN * HH + NN * 3;
    prep_kernel<<<(total + 255) / 256, 256>>>(ei, ew1, ew2, cw1);
    edge_kernel<<<nsm, ETHR, SMEM_EDGE>>>(h, x, ei, ew1, eb1, eb2, cb1, cw2);
    node_kernel<<<(NN + NTILE - 1) / NTILE, NTHR, smem_node>>>(h, x, nw1, nb1,
                                                               nw2, nb2, out);
}

// round 14
// speedup vs baseline: 1.0687x; 1.0687x over previous
#include <cuda_runtime.h>
#include <cuda_fp16.h>

#define NN   20000
#define EE   640000
#define HH   128
#define MT   256            // edges per tile (MMA M)
#define ETHR 512            // 16 warps, each 32x64 warp-tile

#define NTILE 64            // node kernel tile
#define NPAD  132
#define NTHR  256

typedef unsigned int u32;
typedef unsigned long long u64;

// Padded fp16 row length (136*2=272B -> ldmatrix conflict-free phases)
#define KP   136
#define IMG  (128 * KP)            // one [128][136] fp16 weight image (elements)
#define STAGE_BYTES (IMG * 2)      // 34816 B per weight stage
#define IMGA (256 * KP)            // activation image [256][136] (elements)

// ---------------- device scratch (allocation-free rule) ----------------
__device__ __align__(16) float g_m_i[NN * HH];
__device__ __align__(16) float g_xupd[NN * 3];
__device__ int g_is64;
// 4 weight stages (W1a, W1b, W2, W3), each one [128][136] fp16 image [n][k]
__device__ __align__(16) __half g_wb[4 * IMG];

__device__ __forceinline__ float silu_f(float v) {
    return v * (1.0f / (1.0f + __expf(-v)));
}

// ---------------- mma.sync helpers (baseline ISA) ----------------
__device__ __forceinline__ u32 smem_u32(const void* p) {
    u32 a;
    asm("{ .reg .u64 t; cvta.to.shared.u64 t, %1; cvt.u32.u64 %0, t; }"
        : "=r"(a) : "l"(p));
    return a;
}
__device__ __forceinline__ void ldm4(u32* r, u32 addr) {
    asm volatile("ldmatrix.sync.aligned.m8n8.x4.shared.b16 {%0,%1,%2,%3}, [%4];"
                 : "=r"(r[0]), "=r"(r[1]), "=r"(r[2]), "=r"(r[3]) : "r"(addr));
}
__device__ __forceinline__ void mma_f16(float* c, const u32* a, u32 b0, u32 b1) {
    asm volatile(
        "mma.sync.aligned.m16n8k16.row.col.f32.f16.f16.f32 "
        "{%0,%1,%2,%3}, {%4,%5,%6,%7}, {%8,%9}, {%0,%1,%2,%3};"
        : "+f"(c[0]), "+f"(c[1]), "+f"(c[2]), "+f"(c[3])
        : "r"(a[0]), "r"(a[1]), "r"(a[2]), "r"(a[3]), "r"(b0), "r"(b1));
}
// store (a,b) as half2 into the activation image
__device__ __forceinline__ void store_act(char* A, int m, int n, float a, float b) {
    __half2 p = __floats2half2_rn(a, b);
    *(u32*)(A + (u32)(m * KP + n) * 2) = *(u32*)&p;
}

// cp.async weight staging: one 34816B stage image -> smem, one commit group
__device__ __forceinline__ void stage_w(u32 dst, const __half* src, int tid) {
    const char* g = (const char*)src;
#pragma unroll
    for (int i = 0; i < 5; i++) {
        int idx = tid + i * ETHR;           // need 0..2175
        if (idx < 2176)
            asm volatile("cp.async.cg.shared.global [%0], [%1], 16;"
                         :: "r"(dst + idx * 16), "l"(g + (size_t)idx * 16) : "memory");
    }
    asm volatile("cp.async.commit_group;" ::: "memory");
}
template <int N> __device__ __forceinline__ void cp_wait() {
    asm volatile("cp.async.wait_group %0;" :: "n"(N) : "memory");
}

// ---------------------------------------------------------------------------
// Kernel 0: zero accumulators, detect index width, bake fp16 weight images
// [n][k] padded to KP (B^T, k contiguous) for ldmatrix.
// ---------------------------------------------------------------------------
__global__ void prep_kernel(const void* ei, const float* ew1,
                            const float* ew2, const float* cw1) {
    int i = blockIdx.x * blockDim.x + threadIdx.x;
    const int total = NN * HH + NN * 3;
    if (i < total) {
        if (i < NN * HH) g_m_i[i] = 0.0f;
        else             g_xupd[i - NN * HH] = 0.0f;
    }
    if (i < 65536) {
        int s = i >> 14, r = i & 16383;
        int k = r >> 7, n = r & 127;
        float v;
        if      (s == 0) v = ew1[k * 128 + n];
        else if (s == 1) v = ew1[(128 + k) * 128 + n];
        else if (s == 2) v = ew2[k * 128 + n];
        else             v = cw1[k * 128 + n];
        g_wb[(size_t)s * IMG + n * KP + k] = __float2half_rn(v);
    }
    if (blockIdx.x == 0 && threadIdx.x == 0) {
        const unsigned* w = (const unsigned*)ei;
        int is64 = 1;
        for (int kk = 0; kk < 32; kk++)
            if (w[2 * kk + 1] != 0u) { is64 = 0; break; }
        g_is64 = is64;
    }
}

// SMEM byte offsets (edge kernel): 4 resident weight stages + A image + misc
#define OFF_W(s) ((s) * STAGE_BYTES)         // 0 .. 139264
#define OFF_A    (4 * STAGE_BYTES)           // 139264
#define OFF_MISC (OFF_A + IMGA * 2)          // 208896
#define SMEM_EDGE (OFF_MISC + 10816)         // 219712

// One K=128 GEMM: warp-tile 32 rows x 64 cols, pure fp16.
// acc[16][4]: idx = rg*8 + 2t(+1); rg = row sub-group (+16 rows), t = n-tile.
// B fragments are shared between the two row groups (halves B LDSM traffic).
__device__ __forceinline__ void gemm_mma(float acc[16][4],
                                         u32 aImg, u32 wB,
                                         int lane, int wm, int nh)
{
    const int rA0 = wm * 32 + (lane & 15);
    const u32 aoff0 = (u32)(rA0 * KP + ((lane & 16) ? 8 : 0)) * 2;
    const u32 aoff1 = aoff0 + 16 * KP * 2;
    const int rB = nh * 64 + ((lane & 16) ? 8 : 0) + (lane & 7);
    const u32 boff = (u32)(rB * KP + ((lane & 8) ? 8 : 0)) * 2;

#pragma unroll
    for (int k0 = 0; k0 < 8; k0++) {
        u32 a0[4], a1[4];
        ldm4(a0, aImg + aoff0 + k0 * 32);
        ldm4(a1, aImg + aoff1 + k0 * 32);
#pragma unroll
        for (int t = 0; t < 4; t++) {
            u32 bh[4];
            ldm4(bh, wB + boff + (u32)t * (16 * KP * 2) + k0 * 32);
            mma_f16(acc[2 * t],         a0, bh[0], bh[1]);
            mma_f16(acc[2 * t + 1],     a0, bh[2], bh[3]);
            mma_f16(acc[8 + 2 * t],     a1, bh[0], bh[1]);
            mma_f16(acc[8 + 2 * t + 1], a1, bh[2], bh[3]);
        }
    }
}

// ---------------------------------------------------------------------------
// Kernel 1: fused edge pipeline (pure fp16 mma.sync, MT=256 tiles)
// ---------------------------------------------------------------------------
__global__ void __launch_bounds__(ETHR, 1) edge_kernel(
    const float* __restrict__ h, const float* __restrict__ x,
    const void* __restrict__ ei,
    const float* __restrict__ ew1,   // radial-row weights (fp32)
    const float* __restrict__ eb1, const float* __restrict__ eb2,
    const float* __restrict__ cb1, const float* __restrict__ cw2)
{
    extern __shared__ char smem[];
    char*  A_img = smem + OFF_A;
    float* s_eb1 = (float*)(smem + OFF_MISC);
    float* s_eb2 = s_eb1 + 128;
    float* s_cb1 = s_eb2 + 128;
    float* s_wl  = s_cb1 + 128;
    float* s_cw2 = s_wl + 128;
    float* s_rad = s_cw2 + 128;          // [256]
    float* s_cd  = s_rad + 256;          // [256][3]
    float* s_part = s_cd + 768;          // [256][2]
    int*   s_row = (int*)(s_part + 512); // [256]
    int*   s_col = s_row + 256;          // [256]

    const int tid  = threadIdx.x;
    const int lane = tid & 31;
    const int warp = tid >> 5;
    const int wm   = warp >> 1;          // 8 row groups of 32
    const int nh   = warp & 1;           // column half (64 cols)
    const int e0   = blockIdx.x * MT;

    const u32 sb = smem_u32(smem);
    const u32 aA = sb + OFF_A;

    // load all 4 weight stages once (groups g0..g3)
    stage_w(sb + OFF_W(0), g_wb,           tid);
    stage_w(sb + OFF_W(1), g_wb + IMG,     tid);
    stage_w(sb + OFF_W(2), g_wb + 2 * IMG, tid);
    stage_w(sb + OFF_W(3), g_wb + 3 * IMG, tid);

    // ---- per-tile metadata ----
    if (tid < MT) {
        int e = e0 + tid;
        int r, c;
        if (g_is64) {
            const long long* p = (const long long*)ei;
            r = (int)p[e]; c = (int)p[EE + e];
        } else {
            const int* p = (const int*)ei;
            r = p[e]; c = p[EE + e];
        }
        s_row[tid] = r; s_col[tid] = c;
        float dx = x[r * 3 + 0] - x[c * 3 + 0];
        float dy = x[r * 3 + 1] - x[c * 3 + 1];
        float dz = x[r * 3 + 2] - x[c * 3 + 2];
        s_cd[tid * 3 + 0] = dx; s_cd[tid * 3 + 1] = dy; s_cd[tid * 3 + 2] = dz;
        s_rad[tid] = dx * dx + dy * dy + dz * dz;
    }
    if (tid < 128) {
        s_eb1[tid] = eb1[tid];
        s_eb2[tid] = eb2[tid];
        s_cb1[tid] = cb1[tid];
        s_wl[tid]  = ew1[256 * 128 + tid];
        s_cw2[tid] = cw2[tid];
    }
    __syncthreads();                      // metadata visible

    const int l4 = lane >> 2, l2 = lane & 3;
    const int m00 = wm * 32 + l4, m01 = m00 + 8, m10 = m00 + 16, m11 = m00 + 24;

    float acc[16][4];
#pragma unroll
    for (int t = 0; t < 16; t++)
#pragma unroll
        for (int j = 0; j < 4; j++) acc[t][j] = 0.0f;

    // ---- gather h[row] -> A (each thread: one row half = 64 cols) ----
    {
        int r = tid >> 1, q = (tid & 1) * 64;
        const float4* hb = (const float4*)(h + (size_t)s_row[r] * HH + q);
#pragma unroll
        for (int i = 0; i < 16; i++) {
            float4 f = hb[i];
            int c = q + i * 4;
            store_act(A_img, r, c,     f.x, f.y);
            store_act(A_img, r, c + 2, f.z, f.w);
        }
    }
    cp_wait<3>();                         // W1a landed
    __syncthreads();
    gemm_mma(acc, aA, sb + OFF_W(0), lane, wm, nh);
    __syncthreads();

    // ---- gather h[col] -> A ----
    {
        int r = tid >> 1, q = (tid & 1) * 64;
        const float4* hb = (const float4*)(h + (size_t)s_col[r] * HH + q);
#pragma unroll
        for (int i = 0; i < 16; i++) {
            float4 f = hb[i];
            int c = q + i * 4;
            store_act(A_img, r, c,     f.x, f.y);
            store_act(A_img, r, c + 2, f.z, f.w);
        }
    }
    cp_wait<2>();                         // W1b landed
    __syncthreads();
    gemm_mma(acc, aA, sb + OFF_W(1), lane, wm, nh);
    __syncthreads();

    // ---- epi1: t1 = silu(acc + eb1 + rad*wl) -> A ----
    {
        float r0 = s_rad[m00], r1 = s_rad[m01], r2 = s_rad[m10], r3 = s_rad[m11];
#pragma unroll
        for (int rg = 0; rg < 2; rg++) {
            float ra = rg ? r2 : r0, rb = rg ? r3 : r1;
            int ma = rg ? m10 : m00, mb = rg ? m11 : m01;
#pragma unroll
            for (int nt = 0; nt < 8; nt++) {
                float* a = acc[rg * 8 + nt];
                int n = nh * 64 + nt * 8 + 2 * l2;
                float b0 = s_eb1[n], b1 = s_eb1[n + 1];
                float w0 = s_wl[n],  w1 = s_wl[n + 1];
                float v00 = silu_f(a[0] + b0 + ra * w0);
                float v01 = silu_f(a[1] + b1 + ra * w1);
                float v10 = silu_f(a[2] + b0 + rb * w0);
                float v11 = silu_f(a[3] + b1 + rb * w1);
                store_act(A_img, ma, n, v00, v01);
                store_act(A_img, mb, n, v10, v11);
                a[0] = a[1] = a[2] = a[3] = 0.0f;
            }
        }
    }
    cp_wait<1>();                         // W2 landed
    __syncthreads();
    gemm_mma(acc, aA, sb + OFF_W(2), lane, wm, nh);
    __syncthreads();

    // ---- epi2: m_ij = silu(acc + eb2); m_i atomics; -> A ----
    {
        float* g0p = g_m_i + (size_t)s_row[m00] * HH;
        float* g1p = g_m_i + (size_t)s_row[m01] * HH;
        float* g2p = g_m_i + (size_t)s_row[m10] * HH;
        float* g3p = g_m_i + (size_t)s_row[m11] * HH;
#pragma unroll
        for (int rg = 0; rg < 2; rg++) {
            int ma = rg ? m10 : m00, mb = rg ? m11 : m01;
            float* ga = rg ? g2p : g0p;
            float* gb = rg ? g3p : g1p;
#pragma unroll
            for (int nt = 0; nt < 8; nt++) {
                float* a = acc[rg * 8 + nt];
                int n = nh * 64 + nt * 8 + 2 * l2;
                float b0 = s_eb2[n], b1 = s_eb2[n + 1];
                float v00 = silu_f(a[0] + b0);
                float v01 = silu_f(a[1] + b1);
                float v10 = silu_f(a[2] + b0);
                float v11 = silu_f(a[3] + b1);
                atomicAdd(ga + n,     v00);
                atomicAdd(ga + n + 1, v01);
                atomicAdd(gb + n,     v10);
                atomicAdd(gb + n + 1, v11);
                store_act(A_img, ma, n, v00, v01);
                store_act(A_img, mb, n, v10, v11);
                a[0] = a[1] = a[2] = a[3] = 0.0f;
            }
        }
    }
    cp_wait<0>();                         // W3 landed
    __syncthreads();
    gemm_mma(acc, aA, sb + OFF_W(3), lane, wm, nh);

    // ---- epi3: coord_weight = silu(acc + cb1) . cw2 ----
    {
#pragma unroll
        for (int rg = 0; rg < 2; rg++) {
            float p0 = 0.0f, p1 = 0.0f;
#pragma unroll
            for (int nt = 0; nt < 8; nt++) {
                float* a = acc[rg * 8 + nt];
                int n = nh * 64 + nt * 8 + 2 * l2;
                float b0 = s_cb1[n], b1 = s_cb1[n + 1];
                float c0 = s_cw2[n], c1 = s_cw2[n + 1];
                p0 += silu_f(a[0] + b0) * c0 + silu_f(a[1] + b1) * c1;
                p1 += silu_f(a[2] + b0) * c0 + silu_f(a[3] + b1) * c1;
            }
            p0 += __shfl_xor_sync(0xffffffffu, p0, 1);
            p0 += __shfl_xor_sync(0xffffffffu, p0, 2);
            p1 += __shfl_xor_sync(0xffffffffu, p1, 1);
            p1 += __shfl_xor_sync(0xffffffffu, p1, 2);
            if (l2 == 0) {
                int ma = rg ? m10 : m00, mb = rg ? m11 : m01;
                s_part[ma * 2 + nh] = p0;
                s_part[mb * 2 + nh] = p1;
            }
        }
    }
    __syncthreads();

    if (tid < MT) {
        float w = s_part[tid * 2] + s_part[tid * 2 + 1];
        int r = s_row[tid];
        atomicAdd(&g_xupd[r * 3 + 0], s_cd[tid * 3 + 0] * w);
        atomicAdd(&g_xupd[r * 3 + 1], s_cd[tid * 3 + 1] * w);
        atomicAdd(&g_xupd[r * 3 + 2], s_cd[tid * 3 + 2] * w);
    }
}

// ---------------------------------------------------------------------------
// Kernel 2: node MLP + residual + x epilogue (SIMT f32x2 — small workload)
// ---------------------------------------------------------------------------
__device__ __forceinline__ void fma2(u64& d, u64 a, u64 b) {
    asm("fma.rn.f32x2 %0, %1, %2, %0;" : "+l"(d) : "l"(a), "l"(b));
}
__device__ __forceinline__ float red2(u64 v) {
    return __uint_as_float((unsigned)v) + __uint_as_float((unsigned)(v >> 32));
}

__device__ __forceinline__ void gemm2(u64 acc[4][8],
                                      const float* __restrict__ W,
                                      const float* __restrict__ Sin,
                                      float2* __restrict__ wbuf2,
                                      int tid, int r0, int c0)
{
#pragma unroll 1
    for (int k0 = 0; k0 < 128; k0 += 16) {
        __syncthreads();
#pragma unroll
        for (int t = 0; t < 4; t++) {
            int idx = tid + t * 256;
            int k2 = idx >> 7, j = idx & 127;
            wbuf2[idx] = make_float2(W[(k0 + 2 * k2) * HH + j],
                                     W[(k0 + 2 * k2 + 1) * HH + j]);
        }
        __syncthreads();
#pragma unroll
        for (int k2 = 0; k2 < 8; k2++) {
            u64 bb[8], aa[4];
#pragma unroll
            for (int m = 0; m < 8; m++)
                bb[m] = *(const u64*)&wbuf2[k2 * 128 + c0 + 16 * m];
#pragma unroll
            for (int i = 0; i < 4; i++)
                aa[i] = *(const u64*)&Sin[(r0 + i) * NPAD + k0 + 2 * k2];
#pragma unroll
            for (int i = 0; i < 4; i++)
#pragma unroll
                for (int m = 0; m < 8; m++)
                    fma2(acc[i][m], aa[i], bb[m]);
        }
    }
}

__global__ void __launch_bounds__(NTHR, 2) node_kernel(
    const float* __restrict__ h, const float* __restrict__ x,
    const float* __restrict__ nw1, const float* __restrict__ nb1,
    const float* __restrict__ nw2, const float* __restrict__ nb2,
    float* __restrict__ out)
{
    extern __shared__ float smemf[];
    float*  S_h   = smemf;
    float*  S_m   = S_h + NTILE * NPAD;
    float*  S_act = S_m + NTILE * NPAD;
    float2* wbuf2 = (float2*)(S_act + NTILE * NPAD);

    const int tid = threadIdx.x;
    const int n0  = blockIdx.x * NTILE;

    const float4* h4 = (const float4*)h;
    const float4* m4 = (const float4*)g_m_i;
    for (int i = tid; i < NTILE * 32; i += NTHR) {
        int rl = i >> 5, q = i & 31;
        int r = n0 + rl;
        float4 vh = make_float4(0.f, 0.f, 0.f, 0.f);
        float4 vm = vh;
        if (r < NN) { vh = h4[r * 32 + q]; vm = m4[r * 32 + q]; }
        *(float4*)&S_h[rl * NPAD + q * 4] = vh;
        *(float4*)&S_m[rl * NPAD + q * 4] = vm;
    }

    const int r0 = (tid >> 4) * 4;
    const int c0 = tid & 15;
    u64 acc[4][8];

#pragma unroll
    for (int m = 0; m < 8; m++) {
        float b = nb1[c0 + 16 * m];
#pragma unroll
        for (int i = 0; i < 4; i++) acc[i][m] = (u64)__float_as_uint(b);
    }
    gemm2(acc, nw1,            S_h, wbuf2, tid, r0, c0);
    gemm2(acc, nw1 + 128 * HH, S_m, wbuf2, tid, r0, c0);

#pragma unroll
    for (int i = 0; i < 4; i++)
#pragma unroll
        for (int m = 0; m < 8; m++)
            S_act[(r0 + i) * NPAD + c0 + 16 * m] = silu_f(red2(acc[i][m]));

#pragma unroll
    for (int m = 0; m < 8; m++) {
        float b = nb2[c0 + 16 * m];
#pragma unroll
        for (int i = 0; i < 4; i++) acc[i][m] = (u64)__float_as_uint(b);
    }
    gemm2(acc, nw2, S_act, wbuf2, tid, r0, c0);

#pragma unroll
    for (int i = 0; i < 4; i++) {
        int r = n0 + r0 + i;
        if (r < NN) {
#pragma unroll
            for (int m = 0; m < 8; m++)
                out[r * HH + c0 + 16 * m] =
                    S_h[(r0 + i) * NPAD + c0 + 16 * m] + red2(acc[i][m]);
        }
    }

    if (tid < NTILE) {
        int r = n0 + tid;
        if (r < NN) {
            const float inv = 1.0f / (float)(NN - 1);
            out[NN * HH + r * 3 + 0] = x[r * 3 + 0] + g_xupd[r * 3 + 0] * inv;
            out[NN * HH + r * 3 + 1] = x[r * 3 + 1] + g_xupd[r * 3 + 1] * inv;
            out[NN * HH + r * 3 + 2] = x[r * 3 + 2] + g_xupd[r * 3 + 2] * inv;
        }
    }
}

// ---------------------------------------------------------------------------

extern "C" void kernel_launch(void* const* d_in, const int* in_sizes, int n_in,
                              void* d_out, int out_size) {
    const float* h   = (const float*)d_in[0];
    const float* x   = (const float*)d_in[1];
    const void*  ei  = d_in[2];
    const float* ew1 = (const float*)d_in[3];
    const float* eb1 = (const float*)d_in[4];
    const float* ew2 = (const float*)d_in[5];
    const float* eb2 = (const float*)d_in[6];
    const float* nw1 = (const float*)d_in[7];
    const float* nb1 = (const float*)d_in[8];
    const float* nw2 = (const float*)d_in[9];
    const float* nb2 = (const float*)d_in[10];
    const float* cw1 = (const float*)d_in[11];
    const float* cb1 = (const float*)d_in[12];
    const float* cw2 = (const float*)d_in[13];
    float* out = (float*)d_out;

    const int smem_node = (3 * NTILE * NPAD) * 4 + 8 * HH * 8;

    cudaFuncSetAttribute(edge_kernel, cudaFuncAttributeMaxDynamicSharedMemorySize, SMEM_EDGE);
    cudaFuncSetAttribute(node_kernel, cudaFuncAttributeMaxDynamicSharedMemorySize, smem_node);

    const int total = NN * HH + NN * 3;
    prep_kernel<<<(total + 255) / 256, 256>>>(ei, ew1, ew2, cw1);
    edge_kernel<<<EE / MT, ETHR, SMEM_EDGE>>>(h, x, ei, ew1, eb1, eb2, cb1, cw2);
    node_kernel<<<(NN + NTILE - 1) / NTILE, NTHR, smem_node>>>(h, x, nw1, nb1,
                                                               nw2, nb2, out);
}

// round 15
// speedup vs baseline: 1.1477x; 1.0739x over previous
#include <cuda_runtime.h>
#include <cuda_fp16.h>

#define NN   20000
#define EE   640000
#define HH   128
#define MT   128            // edges per tile (MMA M)
#define ETHR 512            // 16 warps: 4 row-groups x 4 col-quarters (32x32)
#define NTILES (EE / MT)

#define NTILE 64            // node kernel tile
#define NPAD  132
#define NTHR  256

typedef unsigned int u32;
typedef unsigned long long u64;

// Padded fp16 row length (136*2=272B -> ldmatrix conflict-free phases)
#define KP   136
#define IMG  (128 * KP)            // one [128][136] fp16 image (elements)
#define STAGE_BYTES (IMG * 2)      // 34816 B per weight stage

// ---------------- device scratch (allocation-free rule) ----------------
__device__ __align__(16) float g_m_i[NN * HH];
__device__ __align__(16) float g_xupd[NN * 3];
__device__ int g_is64;
// 4 weight stages (W1a, W1b, W2, W3), each one [128][136] fp16 image [n][k]
__device__ __align__(16) __half g_wb[4 * IMG];

__device__ __forceinline__ float silu_f(float v) {
    return v * (1.0f / (1.0f + __expf(-v)));
}

// ---------------- mma.sync helpers (baseline ISA) ----------------
__device__ __forceinline__ u32 smem_u32(const void* p) {
    u32 a;
    asm("{ .reg .u64 t; cvta.to.shared.u64 t, %1; cvt.u32.u64 %0, t; }"
        : "=r"(a) : "l"(p));
    return a;
}
__device__ __forceinline__ void ldm4(u32* r, u32 addr) {
    asm volatile("ldmatrix.sync.aligned.m8n8.x4.shared.b16 {%0,%1,%2,%3}, [%4];"
                 : "=r"(r[0]), "=r"(r[1]), "=r"(r[2]), "=r"(r[3]) : "r"(addr));
}
__device__ __forceinline__ void mma_f16(float* c, const u32* a, u32 b0, u32 b1) {
    asm volatile(
        "mma.sync.aligned.m16n8k16.row.col.f32.f16.f16.f32 "
        "{%0,%1,%2,%3}, {%4,%5,%6,%7}, {%8,%9}, {%0,%1,%2,%3};"
        : "+f"(c[0]), "+f"(c[1]), "+f"(c[2]), "+f"(c[3])
        : "r"(a[0]), "r"(a[1]), "r"(a[2]), "r"(a[3]), "r"(b0), "r"(b1));
}
// store (a,b) as half2 into the activation image
__device__ __forceinline__ void store_act(char* A, int m, int n, float a, float b) {
    __half2 p = __floats2half2_rn(a, b);
    *(u32*)(A + (u32)(m * KP + n) * 2) = *(u32*)&p;
}

// cp.async weight staging: one 34816B stage image -> smem, one commit group
__device__ __forceinline__ void stage_w(u32 dst, const __half* src, int tid) {
    const char* g = (const char*)src;
#pragma unroll
    for (int i = 0; i < 5; i++) {
        int idx = tid + i * ETHR;           // need 0..2175
        if (idx < 2176)
            asm volatile("cp.async.cg.shared.global [%0], [%1], 16;"
                         :: "r"(dst + idx * 16), "l"(g + (size_t)idx * 16) : "memory");
    }
    asm volatile("cp.async.commit_group;" ::: "memory");
}
template <int N> __device__ __forceinline__ void cp_wait() {
    asm volatile("cp.async.wait_group %0;" :: "n"(N) : "memory");
}

// ---------------------------------------------------------------------------
// Kernel 0: zero accumulators, detect index width, bake fp16 weight images
// [n][k] padded to KP (B^T, k contiguous) for ldmatrix.
// ---------------------------------------------------------------------------
__global__ void prep_kernel(const void* ei, const float* ew1,
                            const float* ew2, const float* cw1) {
    int i = blockIdx.x * blockDim.x + threadIdx.x;
    const int total = NN * HH + NN * 3;
    if (i < total) {
        if (i < NN * HH) g_m_i[i] = 0.0f;
        else             g_xupd[i - NN * HH] = 0.0f;
    }
    if (i < 65536) {
        int s = i >> 14, r = i & 16383;
        int k = r >> 7, n = r & 127;
        float v;
        if      (s == 0) v = ew1[k * 128 + n];
        else if (s == 1) v = ew1[(128 + k) * 128 + n];
        else if (s == 2) v = ew2[k * 128 + n];
        else             v = cw1[k * 128 + n];
        g_wb[(size_t)s * IMG + n * KP + k] = __float2half_rn(v);
    }
    if (blockIdx.x == 0 && threadIdx.x == 0) {
        const unsigned* w = (const unsigned*)ei;
        int is64 = 1;
        for (int kk = 0; kk < 32; kk++)
            if (w[2 * kk + 1] != 0u) { is64 = 0; break; }
        g_is64 = is64;
    }
}

// SMEM byte offsets (edge kernel): 4 resident weight stages + A image + misc
#define OFF_W(s) ((s) * STAGE_BYTES)         // 0 .. 139264
#define OFF_A    (4 * STAGE_BYTES)           // 139264
#define OFF_MISC (OFF_A + IMG * 2)           // 174080
#define SMEM_EDGE (OFF_MISC + 7936)          // 182016

// One K=128 GEMM: warp-tile 32 rows x 32 cols, pure fp16.
// acc[8][4]: idx = rg*4 + nt; rg = row sub-group (+16 rows), nt = n-tile of 8.
// Per k0: 2 A ldm4 + 2 B ldm4 (minimal crossbar traffic at 4x4 warp grid).
__device__ __forceinline__ void gemm_mma(float acc[8][4],
                                         u32 aImg, u32 wB,
                                         int lane, int wm, int nq)
{
    const int rA0 = wm * 32 + (lane & 15);
    const u32 aoff0 = (u32)(rA0 * KP + ((lane & 16) ? 8 : 0)) * 2;
    const u32 aoff1 = aoff0 + 16 * KP * 2;
    const int rB = nq * 32 + ((lane & 16) ? 8 : 0) + (lane & 7);
    const u32 boff = (u32)(rB * KP + ((lane & 8) ? 8 : 0)) * 2;

#pragma unroll
    for (int k0 = 0; k0 < 8; k0++) {
        u32 a0[4], a1[4];
        ldm4(a0, aImg + aoff0 + k0 * 32);
        ldm4(a1, aImg + aoff1 + k0 * 32);
#pragma unroll
        for (int t = 0; t < 2; t++) {
            u32 bh[4];
            ldm4(bh, wB + boff + (u32)t * (16 * KP * 2) + k0 * 32);
            mma_f16(acc[2 * t],         a0, bh[0], bh[1]);
            mma_f16(acc[2 * t + 1],     a0, bh[2], bh[3]);
            mma_f16(acc[4 + 2 * t],     a1, bh[0], bh[1]);
            mma_f16(acc[4 + 2 * t + 1], a1, bh[2], bh[3]);
        }
    }
}

// ---------------------------------------------------------------------------
// Kernel 1: fused edge pipeline (pure fp16 mma.sync, 4x4 warp grid)
// ---------------------------------------------------------------------------
__global__ void __launch_bounds__(ETHR, 1) edge_kernel(
    const float* __restrict__ h, const float* __restrict__ x,
    const void* __restrict__ ei,
    const float* __restrict__ ew1,   // radial-row weights (fp32)
    const float* __restrict__ eb1, const float* __restrict__ eb2,
    const float* __restrict__ cb1, const float* __restrict__ cw2)
{
    extern __shared__ char smem[];
    char*  A_img = smem + OFF_A;
    float* s_eb1 = (float*)(smem + OFF_MISC);
    float* s_eb2 = s_eb1 + 128;
    float* s_cb1 = s_eb2 + 128;
    float* s_wl  = s_cb1 + 128;
    float* s_cw2 = s_wl + 128;
    float* s_rad = s_cw2 + 128;          // [128]
    float* s_cd  = s_rad + 128;          // [128][3]
    float* s_part = s_cd + 384;          // [128][4]
    int*   s_row = (int*)(s_part + 512); // [128]
    int*   s_col = s_row + 128;          // [128]

    const int tid  = threadIdx.x;
    const int lane = tid & 31;
    const int warp = tid >> 5;
    const int wm   = warp >> 2;          // 4 row groups of 32
    const int nq   = warp & 3;           // 4 column quarters of 32
    const int e0   = blockIdx.x * MT;

    const u32 sb = smem_u32(smem);
    const u32 aA = sb + OFF_A;

    // load all 4 weight stages once (groups g0..g3)
    stage_w(sb + OFF_W(0), g_wb,           tid);
    stage_w(sb + OFF_W(1), g_wb + IMG,     tid);
    stage_w(sb + OFF_W(2), g_wb + 2 * IMG, tid);
    stage_w(sb + OFF_W(3), g_wb + 3 * IMG, tid);

    // ---- per-tile metadata ----
    if (tid < MT) {
        int e = e0 + tid;
        int r, c;
        if (g_is64) {
            const long long* p = (const long long*)ei;
            r = (int)p[e]; c = (int)p[EE + e];
        } else {
            const int* p = (const int*)ei;
            r = p[e]; c = p[EE + e];
        }
        s_row[tid] = r; s_col[tid] = c;
        float dx = x[r * 3 + 0] - x[c * 3 + 0];
        float dy = x[r * 3 + 1] - x[c * 3 + 1];
        float dz = x[r * 3 + 2] - x[c * 3 + 2];
        s_cd[tid * 3 + 0] = dx; s_cd[tid * 3 + 1] = dy; s_cd[tid * 3 + 2] = dz;
        s_rad[tid] = dx * dx + dy * dy + dz * dz;
        s_eb1[tid] = eb1[tid];
        s_eb2[tid] = eb2[tid];
        s_cb1[tid] = cb1[tid];
        s_wl[tid]  = ew1[256 * 128 + tid];
        s_cw2[tid] = cw2[tid];
    }
    __syncthreads();                      // metadata visible

    const int l4 = lane >> 2, l2 = lane & 3;
    const int m00 = wm * 32 + l4, m01 = m00 + 8, m10 = m00 + 16, m11 = m00 + 24;

    float acc[8][4];
#pragma unroll
    for (int t = 0; t < 8; t++)
#pragma unroll
        for (int j = 0; j < 4; j++) acc[t][j] = 0.0f;

    // ---- gather h[row] -> A (each thread: one row, 32 cols) ----
    {
        int r = tid >> 2, q = (tid & 3) * 32;
        const float4* hb = (const float4*)(h + (size_t)s_row[r] * HH + q);
#pragma unroll
        for (int i = 0; i < 8; i++) {
            float4 f = hb[i];
            int c = q + i * 4;
            store_act(A_img, r, c,     f.x, f.y);
            store_act(A_img, r, c + 2, f.z, f.w);
        }
    }
    cp_wait<3>();                         // W1a landed
    __syncthreads();
    gemm_mma(acc, aA, sb + OFF_W(0), lane, wm, nq);
    __syncthreads();

    // ---- gather h[col] -> A ----
    {
        int r = tid >> 2, q = (tid & 3) * 32;
        const float4* hb = (const float4*)(h + (size_t)s_col[r] * HH + q);
#pragma unroll
        for (int i = 0; i < 8; i++) {
            float4 f = hb[i];
            int c = q + i * 4;
            store_act(A_img, r, c,     f.x, f.y);
            store_act(A_img, r, c + 2, f.z, f.w);
        }
    }
    cp_wait<2>();                         // W1b landed
    __syncthreads();
    gemm_mma(acc, aA, sb + OFF_W(1), lane, wm, nq);
    __syncthreads();

    // ---- epi1: t1 = silu(acc + eb1 + rad*wl) -> A ----
    {
        float r0 = s_rad[m00], r1 = s_rad[m01], r2 = s_rad[m10], r3 = s_rad[m11];
#pragma unroll
        for (int rg = 0; rg < 2; rg++) {
            float ra = rg ? r2 : r0, rb = rg ? r3 : r1;
            int ma = rg ? m10 : m00, mb = rg ? m11 : m01;
#pragma unroll
            for (int nt = 0; nt < 4; nt++) {
                float* a = acc[rg * 4 + nt];
                int n = nq * 32 + nt * 8 + 2 * l2;
                float b0 = s_eb1[n], b1 = s_eb1[n + 1];
                float w0 = s_wl[n],  w1 = s_wl[n + 1];
                float v00 = silu_f(a[0] + b0 + ra * w0);
                float v01 = silu_f(a[1] + b1 + ra * w1);
                float v10 = silu_f(a[2] + b0 + rb * w0);
                float v11 = silu_f(a[3] + b1 + rb * w1);
                store_act(A_img, ma, n, v00, v01);
                store_act(A_img, mb, n, v10, v11);
                a[0] = a[1] = a[2] = a[3] = 0.0f;
            }
        }
    }
    cp_wait<1>();                         // W2 landed
    __syncthreads();
    gemm_mma(acc, aA, sb + OFF_W(2), lane, wm, nq);
    __syncthreads();

    // ---- epi2: m_ij = silu(acc + eb2); m_i atomics; -> A ----
    {
        float* g0p = g_m_i + (size_t)s_row[m00] * HH;
        float* g1p = g_m_i + (size_t)s_row[m01] * HH;
        float* g2p = g_m_i + (size_t)s_row[m10] * HH;
        float* g3p = g_m_i + (size_t)s_row[m11] * HH;
#pragma unroll
        for (int rg = 0; rg < 2; rg++) {
            int ma = rg ? m10 : m00, mb = rg ? m11 : m01;
            float* ga = rg ? g2p : g0p;
            float* gb = rg ? g3p : g1p;
#pragma unroll
            for (int nt = 0; nt < 4; nt++) {
                float* a = acc[rg * 4 + nt];
                int n = nq * 32 + nt * 8 + 2 * l2;
                float b0 = s_eb2[n], b1 = s_eb2[n + 1];
                float v00 = silu_f(a[0] + b0);
                float v01 = silu_f(a[1] + b1);
                float v10 = silu_f(a[2] + b0);
                float v11 = silu_f(a[3] + b1);
                atomicAdd(ga + n,     v00);
                atomicAdd(ga + n + 1, v01);
                atomicAdd(gb + n,     v10);
                atomicAdd(gb + n + 1, v11);
                store_act(A_img, ma, n, v00, v01);
                store_act(A_img, mb, n, v10, v11);
                a[0] = a[1] = a[2] = a[3] = 0.0f;
            }
        }
    }
    cp_wait<0>();                         // W3 landed
    __syncthreads();
    gemm_mma(acc, aA, sb + OFF_W(3), lane, wm, nq);

    // ---- epi3: coord_weight = silu(acc + cb1) . cw2 (32-col partials) ----
    {
#pragma unroll
        for (int rg = 0; rg < 2; rg++) {
            float p0 = 0.0f, p1 = 0.0f;
#pragma unroll
            for (int nt = 0; nt < 4; nt++) {
                float* a = acc[rg * 4 + nt];
                int n = nq * 32 + nt * 8 + 2 * l2;
                float b0 = s_cb1[n], b1 = s_cb1[n + 1];
                float c0 = s_cw2[n], c1 = s_cw2[n + 1];
                p0 += silu_f(a[0] + b0) * c0 + silu_f(a[1] + b1) * c1;
                p1 += silu_f(a[2] + b0) * c0 + silu_f(a[3] + b1) * c1;
            }
            p0 += __shfl_xor_sync(0xffffffffu, p0, 1);
            p0 += __shfl_xor_sync(0xffffffffu, p0, 2);
            p1 += __shfl_xor_sync(0xffffffffu, p1, 1);
            p1 += __shfl_xor_sync(0xffffffffu, p1, 2);
            if (l2 == 0) {
                int ma = rg ? m10 : m00, mb = rg ? m11 : m01;
                s_part[ma * 4 + nq] = p0;
                s_part[mb * 4 + nq] = p1;
            }
        }
    }
    __syncthreads();

    if (tid < MT) {
        float w = s_part[tid * 4] + s_part[tid * 4 + 1]
                + s_part[tid * 4 + 2] + s_part[tid * 4 + 3];
        int r = s_row[tid];
        atomicAdd(&g_xupd[r * 3 + 0], s_cd[tid * 3 + 0] * w);
        atomicAdd(&g_xupd[r * 3 + 1], s_cd[tid * 3 + 1] * w);
        atomicAdd(&g_xupd[r * 3 + 2], s_cd[tid * 3 + 2] * w);
    }
}

// ---------------------------------------------------------------------------
// Kernel 2: node MLP + residual + x epilogue (SIMT f32x2 — small workload)
// ---------------------------------------------------------------------------
__device__ __forceinline__ void fma2(u64& d, u64 a, u64 b) {
    asm("fma.rn.f32x2 %0, %1, %2, %0;" : "+l"(d) : "l"(a), "l"(b));
}
__device__ __forceinline__ float red2(u64 v) {
    return __uint_as_float((unsigned)v) + __uint_as_float((unsigned)(v >> 32));
}

__device__ __forceinline__ void gemm2(u64 acc[4][8],
                                      const float* __restrict__ W,
                                      const float* __restrict__ Sin,
                                      float2* __restrict__ wbuf2,
                                      int tid, int r0, int c0)
{
#pragma unroll 1
    for (int k0 = 0; k0 < 128; k0 += 16) {
        __syncthreads();
#pragma unroll
        for (int t = 0; t < 4; t++) {
            int idx = tid + t * 256;
            int k2 = idx >> 7, j = idx & 127;
            wbuf2[idx] = make_float2(W[(k0 + 2 * k2) * HH + j],
                                     W[(k0 + 2 * k2 + 1) * HH + j]);
        }
        __syncthreads();
#pragma unroll
        for (int k2 = 0; k2 < 8; k2++) {
            u64 bb[8], aa[4];
#pragma unroll
            for (int m = 0; m < 8; m++)
                bb[m] = *(const u64*)&wbuf2[k2 * 128 + c0 + 16 * m];
#pragma unroll
            for (int i = 0; i < 4; i++)
                aa[i] = *(const u64*)&Sin[(r0 + i) * NPAD + k0 + 2 * k2];
#pragma unroll
            for (int i = 0; i < 4; i++)
#pragma unroll
                for (int m = 0; m < 8; m++)
                    fma2(acc[i][m], aa[i], bb[m]);
        }
    }
}

__global__ void __launch_bounds__(NTHR, 2) node_kernel(
    const float* __restrict__ h, const float* __restrict__ x,
    const float* __restrict__ nw1, const float* __restrict__ nb1,
    const float* __restrict__ nw2, const float* __restrict__ nb2,
    float* __restrict__ out)
{
    extern __shared__ float smemf[];
    float*  S_h   = smemf;
    float*  S_m   = S_h + NTILE * NPAD;
    float*  S_act = S_m + NTILE * NPAD;
    float2* wbuf2 = (float2*)(S_act + NTILE * NPAD);

    const int tid = threadIdx.x;
    const int n0  = blockIdx.x * NTILE;

    const float4* h4 = (const float4*)h;
    const float4* m4 = (const float4*)g_m_i;
    for (int i = tid; i < NTILE * 32; i += NTHR) {
        int rl = i >> 5, q = i & 31;
        int r = n0 + rl;
        float4 vh = make_float4(0.f, 0.f, 0.f, 0.f);
        float4 vm = vh;
        if (r < NN) { vh = h4[r * 32 + q]; vm = m4[r * 32 + q]; }
        *(float4*)&S_h[rl * NPAD + q * 4] = vh;
        *(float4*)&S_m[rl * NPAD + q * 4] = vm;
    }

    const int r0 = (tid >> 4) * 4;
    const int c0 = tid & 15;
    u64 acc[4][8];

#pragma unroll
    for (int m = 0; m < 8; m++) {
        float b = nb1[c0 + 16 * m];
#pragma unroll
        for (int i = 0; i < 4; i++) acc[i][m] = (u64)__float_as_uint(b);
    }
    gemm2(acc, nw1,            S_h, wbuf2, tid, r0, c0);
    gemm2(acc, nw1 + 128 * HH, S_m, wbuf2, tid, r0, c0);

#pragma unroll
    for (int i = 0; i < 4; i++)
#pragma unroll
        for (int m = 0; m < 8; m++)
            S_act[(r0 + i) * NPAD + c0 + 16 * m] = silu_f(red2(acc[i][m]));

#pragma unroll
    for (int m = 0; m < 8; m++) {
        float b = nb2[c0 + 16 * m];
#pragma unroll
        for (int i = 0; i < 4; i++) acc[i][m] = (u64)__float_as_uint(b);
    }
    gemm2(acc, nw2, S_act, wbuf2, tid, r0, c0);

#pragma unroll
    for (int i = 0; i < 4; i++) {
        int r = n0 + r0 + i;
        if (r < NN) {
#pragma unroll
            for (int m = 0; m < 8; m++)
                out[r * HH + c0 + 16 * m] =
                    S_h[(r0 + i) * NPAD + c0 + 16 * m] + red2(acc[i][m]);
        }
    }

    if (tid < NTILE) {
        int r = n0 + tid;
        if (r < NN) {
            const float inv = 1.0f / (float)(NN - 1);
            out[NN * HH + r * 3 + 0] = x[r * 3 + 0] + g_xupd[r * 3 + 0] * inv;
            out[NN * HH + r * 3 + 1] = x[r * 3 + 1] + g_xupd[r * 3 + 1] * inv;
            out[NN * HH + r * 3 + 2] = x[r * 3 + 2] + g_xupd[r * 3 + 2] * inv;
        }
    }
}

// ---------------------------------------------------------------------------

extern "C" void kernel_launch(void* const* d_in, const int* in_sizes, int n_in,
                              void* d_out, int out_size) {
    const float* h   = (const float*)d_in[0];
    const float* x   = (const float*)d_in[1];
    const void*  ei  = d_in[2];
    const float* ew1 = (const float*)d_in[3];
    const float* eb1 = (const float*)d_in[4];
    const float* ew2 = (const float*)d_in[5];
    const float* eb2 = (const float*)d_in[6];
    const float* nw1 = (const float*)d_in[7];
    const float* nb1 = (const float*)d_in[8];
    const float* nw2 = (const float*)d_in[9];
    const float* nb2 = (const float*)d_in[10];
    const float* cw1 = (const float*)d_in[11];
    const float* cb1 = (const float*)d_in[12];
    const float* cw2 = (const float*)d_in[13];
    float* out = (float*)d_out;

    const int smem_node = (3 * NTILE * NPAD) * 4 + 8 * HH * 8;

    cudaFuncSetAttribute(edge_kernel, cudaFuncAttributeMaxDynamicSharedMemorySize, SMEM_EDGE);
    cudaFuncSetAttribute(node_kernel, cudaFuncAttributeMaxDynamicSharedMemorySize, smem_node);

    const int total = NN * HH + NN * 3;
    prep_kernel<<<(total + 255) / 256, 256>>>(ei, ew1, ew2, cw1);
    edge_kernel<<<EE / MT, ETHR, SMEM_EDGE>>>(h, x, ei, ew1, eb1, eb2, cb1, cw2);
    node_kernel<<<(NN + NTILE - 1) / NTILE, NTHR, smem_node>>>(h, x, nw1, nb1,
                                                               nw2, nb2, out);
}

// round 16
// speedup vs baseline: 1.2668x; 1.1037x over previous
#include <cuda_runtime.h>
#include <cuda_fp16.h>

#define NN   20000
#define EE   640000
#define HH   128
#define MT   128            // edges per tile (MMA M)
#define ETHR 256            // 8 warps: 4 row-groups x 2 col-halves (32x64)

#define NTILE 64            // node kernel tile
#define NPAD  132
#define NTHR  256

typedef unsigned int u32;
typedef unsigned long long u64;

// Padded fp16 row length (136*2=272B -> ldmatrix conflict-free phases)
#define KP   136
#define IMG  (128 * KP)            // one [128][136] fp16 image (elements)
#define STAGE_BYTES (IMG * 2)      // 34816 B per weight stage

// ---------------- device scratch (allocation-free rule) ----------------
__device__ __align__(16) float g_m_i[NN * HH];
__device__ __align__(16) float g_xupd[NN * 3];
__device__ int g_is64;
// 4 weight stages (W1a, W1b, W2, W3), each one [128][136] fp16 image [n][k]
__device__ __align__(16) __half g_wb[4 * IMG];

__device__ __forceinline__ float silu_f(float v) {
    return v * (1.0f / (1.0f + __expf(-v)));
}

// ---------------- mma.sync helpers (baseline ISA) ----------------
__device__ __forceinline__ u32 smem_u32(const void* p) {
    u32 a;
    asm("{ .reg .u64 t; cvta.to.shared.u64 t, %1; cvt.u32.u64 %0, t; }"
        : "=r"(a) : "l"(p));
    return a;
}
__device__ __forceinline__ void ldm4(u32* r, u32 addr) {
    asm volatile("ldmatrix.sync.aligned.m8n8.x4.shared.b16 {%0,%1,%2,%3}, [%4];"
                 : "=r"(r[0]), "=r"(r[1]), "=r"(r[2]), "=r"(r[3]) : "r"(addr));
}
__device__ __forceinline__ void mma_f16(float* c, const u32* a, u32 b0, u32 b1) {
    asm volatile(
        "mma.sync.aligned.m16n8k16.row.col.f32.f16.f16.f32 "
        "{%0,%1,%2,%3}, {%4,%5,%6,%7}, {%8,%9}, {%0,%1,%2,%3};"
        : "+f"(c[0]), "+f"(c[1]), "+f"(c[2]), "+f"(c[3])
        : "r"(a[0]), "r"(a[1]), "r"(a[2]), "r"(a[3]), "r"(b0), "r"(b1));
}
// store (a,b) as half2 into the activation image
__device__ __forceinline__ void store_act(char* A, int m, int n, float a, float b) {
    __half2 p = __floats2half2_rn(a, b);
    *(u32*)(A + (u32)(m * KP + n) * 2) = *(u32*)&p;
}

// cp.async weight staging: one 34816B stage image -> smem, one commit group
__device__ __forceinline__ void stage_w(u32 dst, const __half* src, int tid) {
    const char* g = (const char*)src;
#pragma unroll
    for (int i = 0; i < 9; i++) {
        int idx = tid + i * ETHR;           // need 0..2175
        if (idx < 2176)
            asm volatile("cp.async.cg.shared.global [%0], [%1], 16;"
                         :: "r"(dst + idx * 16), "l"(g + (size_t)idx * 16) : "memory");
    }
    asm volatile("cp.async.commit_group;" ::: "memory");
}
template <int N> __device__ __forceinline__ void cp_wait() {
    asm volatile("cp.async.wait_group %0;" :: "n"(N) : "memory");
}

// ---------------------------------------------------------------------------
// Kernel 0: zero accumulators, detect index width, bake fp16 weight images
// [n][k] padded to KP (B^T, k contiguous) for ldmatrix.
// ---------------------------------------------------------------------------
__global__ void prep_kernel(const void* ei, const float* ew1,
                            const float* ew2, const float* cw1) {
    int i = blockIdx.x * blockDim.x + threadIdx.x;
    const int total = NN * HH + NN * 3;
    if (i < total) {
        if (i < NN * HH) g_m_i[i] = 0.0f;
        else             g_xupd[i - NN * HH] = 0.0f;
    }
    if (i < 65536) {
        int s = i >> 14, r = i & 16383;
        int k = r >> 7, n = r & 127;
        float v;
        if      (s == 0) v = ew1[k * 128 + n];
        else if (s == 1) v = ew1[(128 + k) * 128 + n];
        else if (s == 2) v = ew2[k * 128 + n];
        else             v = cw1[k * 128 + n];
        g_wb[(size_t)s * IMG + n * KP + k] = __float2half_rn(v);
    }
    if (blockIdx.x == 0 && threadIdx.x == 0) {
        const unsigned* w = (const unsigned*)ei;
        int is64 = 1;
        for (int kk = 0; kk < 32; kk++)
            if (w[2 * kk + 1] != 0u) { is64 = 0; break; }
        g_is64 = is64;
    }
}

// SMEM byte offsets (edge kernel): 2 weight buffers (dbuf) + A image + misc
#define OFF_W0   0
#define OFF_W1   STAGE_BYTES                 // 34816
#define OFF_A    (2 * STAGE_BYTES)           // 69632
#define OFF_MISC (3 * STAGE_BYTES)           // 104448
#define SMEM_EDGE (OFF_MISC + 6656)          // 111104  (2 CTAs/SM: 217 KB)

// One K=128 GEMM: warp-tile 32 rows x 64 cols, pure fp16.
// acc[16][4]: idx = rg*8 + 2t(+1); rg = row sub-group (+16 rows), t = n-tile.
// B fragments shared between the two row groups.
__device__ __forceinline__ void gemm_mma(float acc[16][4],
                                         u32 aImg, u32 wB,
                                         int lane, int wm, int nh)
{
    const int rA0 = wm * 32 + (lane & 15);
    const u32 aoff0 = (u32)(rA0 * KP + ((lane & 16) ? 8 : 0)) * 2;
    const u32 aoff1 = aoff0 + 16 * KP * 2;
    const int rB = nh * 64 + ((lane & 16) ? 8 : 0) + (lane & 7);
    const u32 boff = (u32)(rB * KP + ((lane & 8) ? 8 : 0)) * 2;

#pragma unroll
    for (int k0 = 0; k0 < 8; k0++) {
        u32 a0[4], a1[4];
        ldm4(a0, aImg + aoff0 + k0 * 32);
        ldm4(a1, aImg + aoff1 + k0 * 32);
#pragma unroll
        for (int t = 0; t < 4; t++) {
            u32 bh[4];
            ldm4(bh, wB + boff + (u32)t * (16 * KP * 2) + k0 * 32);
            mma_f16(acc[2 * t],         a0, bh[0], bh[1]);
            mma_f16(acc[2 * t + 1],     a0, bh[2], bh[3]);
            mma_f16(acc[8 + 2 * t],     a1, bh[0], bh[1]);
            mma_f16(acc[8 + 2 * t + 1], a1, bh[2], bh[3]);
        }
    }
}

// ---------------------------------------------------------------------------
// Kernel 1: fused edge pipeline (fp16 mma.sync, 2 CTAs/SM for overlap)
// ---------------------------------------------------------------------------
__global__ void __launch_bounds__(ETHR, 2) edge_kernel(
    const float* __restrict__ h, const float* __restrict__ x,
    const void* __restrict__ ei,
    const float* __restrict__ ew1,   // radial-row weights (fp32)
    const float* __restrict__ eb1, const float* __restrict__ eb2,
    const float* __restrict__ cb1, const float* __restrict__ cw2)
{
    extern __shared__ char smem[];
    char*  A_img = smem + OFF_A;
    float* s_eb1 = (float*)(smem + OFF_MISC);
    float* s_eb2 = s_eb1 + 128;
    float* s_cb1 = s_eb2 + 128;
    float* s_wl  = s_cb1 + 128;
    float* s_cw2 = s_wl + 128;
    float* s_rad = s_cw2 + 128;          // [128]
    float* s_cd  = s_rad + 128;          // [128][3]
    float* s_part = s_cd + 384;          // [128][2]
    int*   s_row = (int*)(s_part + 256); // [128]
    int*   s_col = s_row + 128;          // [128]

    const int tid  = threadIdx.x;
    const int lane = tid & 31;
    const int warp = tid >> 5;
    const int wm   = warp >> 1;          // 4 row groups of 32
    const int nh   = warp & 1;           // column half (64 cols)
    const int e0   = blockIdx.x * MT;

    const u32 sb  = smem_u32(smem);
    const u32 w0A = sb + OFF_W0, w1A = sb + OFF_W1;
    const u32 aA  = sb + OFF_A;

    // kick off W1a / W1b loads immediately (groups g0, g1)
    stage_w(w0A, g_wb,       tid);
    stage_w(w1A, g_wb + IMG, tid);

    // ---- per-tile metadata ----
    if (tid < MT) {
        int e = e0 + tid;
        int r, c;
        if (g_is64) {
            const long long* p = (const long long*)ei;
            r = (int)p[e]; c = (int)p[EE + e];
        } else {
            const int* p = (const int*)ei;
            r = p[e]; c = p[EE + e];
        }
        s_row[tid] = r; s_col[tid] = c;
        float dx = x[r * 3 + 0] - x[c * 3 + 0];
        float dy = x[r * 3 + 1] - x[c * 3 + 1];
        float dz = x[r * 3 + 2] - x[c * 3 + 2];
        s_cd[tid * 3 + 0] = dx; s_cd[tid * 3 + 1] = dy; s_cd[tid * 3 + 2] = dz;
        s_rad[tid] = dx * dx + dy * dy + dz * dz;
        s_eb1[tid] = eb1[tid];
        s_eb2[tid] = eb2[tid];
        s_cb1[tid] = cb1[tid];
        s_wl[tid]  = ew1[256 * 128 + tid];
        s_cw2[tid] = cw2[tid];
    }
    __syncthreads();                      // metadata visible

    const int l4 = lane >> 2, l2 = lane & 3;
    const int m00 = wm * 32 + l4, m01 = m00 + 8, m10 = m00 + 16, m11 = m00 + 24;

    float acc[16][4];
#pragma unroll
    for (int t = 0; t < 16; t++)
#pragma unroll
        for (int j = 0; j < 4; j++) acc[t][j] = 0.0f;

    // ---- gather h[row] -> A (each thread: one row half = 64 cols) ----
    {
        int r = tid >> 1, q = (tid & 1) * 64;
        const float4* hb = (const float4*)(h + (size_t)s_row[r] * HH + q);
#pragma unroll
        for (int i = 0; i < 16; i++) {
            float4 f = hb[i];
            int c = q + i * 4;
            store_act(A_img, r, c,     f.x, f.y);
            store_act(A_img, r, c + 2, f.z, f.w);
        }
    }
    cp_wait<1>();                         // g0 (W1a) landed
    __syncthreads();
    gemm_mma(acc, aA, w0A, lane, wm, nh);
    __syncthreads();

    // ---- prefetch W2 -> buf0; gather h[col] -> A ----
    stage_w(w0A, g_wb + 2 * IMG, tid);    // g2
    {
        int r = tid >> 1, q = (tid & 1) * 64;
        const float4* hb = (const float4*)(h + (size_t)s_col[r] * HH + q);
#pragma unroll
        for (int i = 0; i < 16; i++) {
            float4 f = hb[i];
            int c = q + i * 4;
            store_act(A_img, r, c,     f.x, f.y);
            store_act(A_img, r, c + 2, f.z, f.w);
        }
    }
    cp_wait<1>();                         // g1 (W1b) landed
    __syncthreads();
    gemm_mma(acc, aA, w1A, lane, wm, nh);
    __syncthreads();

    // ---- prefetch W3 -> buf1; epi1: t1 = silu(acc + eb1 + rad*wl) -> A ----
    stage_w(w1A, g_wb + 3 * IMG, tid);    // g3
    {
        float r0 = s_rad[m00], r1 = s_rad[m01], r2 = s_rad[m10], r3 = s_rad[m11];
#pragma unroll
        for (int rg = 0; rg < 2; rg++) {
            float ra = rg ? r2 : r0, rb = rg ? r3 : r1;
            int ma = rg ? m10 : m00, mb = rg ? m11 : m01;
#pragma unroll
            for (int nt = 0; nt < 8; nt++) {
                float* a = acc[rg * 8 + nt];
                int n = nh * 64 + nt * 8 + 2 * l2;
                float b0 = s_eb1[n], b1 = s_eb1[n + 1];
                float w0 = s_wl[n],  w1 = s_wl[n + 1];
                float v00 = silu_f(a[0] + b0 + ra * w0);
                float v01 = silu_f(a[1] + b1 + ra * w1);
                float v10 = silu_f(a[2] + b0 + rb * w0);
                float v11 = silu_f(a[3] + b1 + rb * w1);
                store_act(A_img, ma, n, v00, v01);
                store_act(A_img, mb, n, v10, v11);
                a[0] = a[1] = a[2] = a[3] = 0.0f;
            }
        }
    }
    cp_wait<1>();                         // g2 (W2) landed
    __syncthreads();
    gemm_mma(acc, aA, w0A, lane, wm, nh);
    __syncthreads();

    // ---- epi2: m_ij = silu(acc + eb2); m_i atomics; -> A ----
    {
        float* g0p = g_m_i + (size_t)s_row[m00] * HH;
        float* g1p = g_m_i + (size_t)s_row[m01] * HH;
        float* g2p = g_m_i + (size_t)s_row[m10] * HH;
        float* g3p = g_m_i + (size_t)s_row[m11] * HH;
#pragma unroll
        for (int rg = 0; rg < 2; rg++) {
            int ma = rg ? m10 : m00, mb = rg ? m11 : m01;
            float* ga = rg ? g2p : g0p;
            float* gb = rg ? g3p : g1p;
#pragma unroll
            for (int nt = 0; nt < 8; nt++) {
                float* a = acc[rg * 8 + nt];
                int n = nh * 64 + nt * 8 + 2 * l2;
                float b0 = s_eb2[n], b1 = s_eb2[n + 1];
                float v00 = silu_f(a[0] + b0);
                float v01 = silu_f(a[1] + b1);
                float v10 = silu_f(a[2] + b0);
                float v11 = silu_f(a[3] + b1);
                atomicAdd(ga + n,     v00);
                atomicAdd(ga + n + 1, v01);
                atomicAdd(gb + n,     v10);
                atomicAdd(gb + n + 1, v11);
                store_act(A_img, ma, n, v00, v01);
                store_act(A_img, mb, n, v10, v11);
                a[0] = a[1] = a[2] = a[3] = 0.0f;
            }
        }
    }
    cp_wait<0>();                         // g3 (W3) landed
    __syncthreads();
    gemm_mma(acc, aA, w1A, lane, wm, nh);

    // ---- epi3: coord_weight = silu(acc + cb1) . cw2 ----
    {
#pragma unroll
        for (int rg = 0; rg < 2; rg++) {
            float p0 = 0.0f, p1 = 0.0f;
#pragma unroll
            for (int nt = 0; nt < 8; nt++) {
                float* a = acc[rg * 8 + nt];
                int n = nh * 64 + nt * 8 + 2 * l2;
                float b0 = s_cb1[n], b1 = s_cb1[n + 1];
                float c0 = s_cw2[n], c1 = s_cw2[n + 1];
                p0 += silu_f(a[0] + b0) * c0 + silu_f(a[1] + b1) * c1;
                p1 += silu_f(a[2] + b0) * c0 + silu_f(a[3] + b1) * c1;
            }
            p0 += __shfl_xor_sync(0xffffffffu, p0, 1);
            p0 += __shfl_xor_sync(0xffffffffu, p0, 2);
            p1 += __shfl_xor_sync(0xffffffffu, p1, 1);
            p1 += __shfl_xor_sync(0xffffffffu, p1, 2);
            if (l2 == 0) {
                int ma = rg ? m10 : m00, mb = rg ? m11 : m01;
                s_part[ma * 2 + nh] = p0;
                s_part[mb * 2 + nh] = p1;
            }
        }
    }
    __syncthreads();

    if (tid < MT) {
        float w = s_part[tid * 2] + s_part[tid * 2 + 1];
        int r = s_row[tid];
        atomicAdd(&g_xupd[r * 3 + 0], s_cd[tid * 3 + 0] * w);
        atomicAdd(&g_xupd[r * 3 + 1], s_cd[tid * 3 + 1] * w);
        atomicAdd(&g_xupd[r * 3 + 2], s_cd[tid * 3 + 2] * w);
    }
}

// ---------------------------------------------------------------------------
// Kernel 2: node MLP + residual + x epilogue (SIMT f32x2 — small workload)
// ---------------------------------------------------------------------------
__device__ __forceinline__ void fma2(u64& d, u64 a, u64 b) {
    asm("fma.rn.f32x2 %0, %1, %2, %0;" : "+l"(d) : "l"(a), "l"(b));
}
__device__ __forceinline__ float red2(u64 v) {
    return __uint_as_float((unsigned)v) + __uint_as_float((unsigned)(v >> 32));
}

__device__ __forceinline__ void gemm2(u64 acc[4][8],
                                      const float* __restrict__ W,
                                      const float* __restrict__ Sin,
                                      float2* __restrict__ wbuf2,
                                      int tid, int r0, int c0)
{
#pragma unroll 1
    for (int k0 = 0; k0 < 128; k0 += 16) {
        __syncthreads();
#pragma unroll
        for (int t = 0; t < 4; t++) {
            int idx = tid + t * 256;
            int k2 = idx >> 7, j = idx & 127;
            wbuf2[idx] = make_float2(W[(k0 + 2 * k2) * HH + j],
                                     W[(k0 + 2 * k2 + 1) * HH + j]);
        }
        __syncthreads();
#pragma unroll
        for (int k2 = 0; k2 < 8; k2++) {
            u64 bb[8], aa[4];
#pragma unroll
            for (int m = 0; m < 8; m++)
                bb[m] = *(const u64*)&wbuf2[k2 * 128 + c0 + 16 * m];
#pragma unroll
            for (int i = 0; i < 4; i++)
                aa[i] = *(const u64*)&Sin[(r0 + i) * NPAD + k0 + 2 * k2];
#pragma unroll
            for (int i = 0; i < 4; i++)
#pragma unroll
                for (int m = 0; m < 8; m++)
                    fma2(acc[i][m], aa[i], bb[m]);
        }
    }
}

__global__ void __launch_bounds__(NTHR, 2) node_kernel(
    const float* __restrict__ h, const float* __restrict__ x,
    const float* __restrict__ nw1, const float* __restrict__ nb1,
    const float* __restrict__ nw2, const float* __restrict__ nb2,
    float* __restrict__ out)
{
    extern __shared__ float smemf[];
    float*  S_h   = smemf;
    float*  S_m   = S_h + NTILE * NPAD;
    float*  S_act = S_m + NTILE * NPAD;
    float2* wbuf2 = (float2*)(S_act + NTILE * NPAD);

    const int tid = threadIdx.x;
    const int n0  = blockIdx.x * NTILE;

    const float4* h4 = (const float4*)h;
    const float4* m4 = (const float4*)g_m_i;
    for (int i = tid; i < NTILE * 32; i += NTHR) {
        int rl = i >> 5, q = i & 31;
        int r = n0 + rl;
        float4 vh = make_float4(0.f, 0.f, 0.f, 0.f);
        float4 vm = vh;
        if (r < NN) { vh = h4[r * 32 + q]; vm = m4[r * 32 + q]; }
        *(float4*)&S_h[rl * NPAD + q * 4] = vh;
        *(float4*)&S_m[rl * NPAD + q * 4] = vm;
    }

    const int r0 = (tid >> 4) * 4;
    const int c0 = tid & 15;
    u64 acc[4][8];

#pragma unroll
    for (int m = 0; m < 8; m++) {
        float b = nb1[c0 + 16 * m];
#pragma unroll
        for (int i = 0; i < 4; i++) acc[i][m] = (u64)__float_as_uint(b);
    }
    gemm2(acc, nw1,            S_h, wbuf2, tid, r0, c0);
    gemm2(acc, nw1 + 128 * HH, S_m, wbuf2, tid, r0, c0);

#pragma unroll
    for (int i = 0; i < 4; i++)
#pragma unroll
        for (int m = 0; m < 8; m++)
            S_act[(r0 + i) * NPAD + c0 + 16 * m] = silu_f(red2(acc[i][m]));

#pragma unroll
    for (int m = 0; m < 8; m++) {
        float b = nb2[c0 + 16 * m];
#pragma unroll
        for (int i = 0; i < 4; i++) acc[i][m] = (u64)__float_as_uint(b);
    }
    gemm2(acc, nw2, S_act, wbuf2, tid, r0, c0);

#pragma unroll
    for (int i = 0; i < 4; i++) {
        int r = n0 + r0 + i;
        if (r < NN) {
#pragma unroll
            for (int m = 0; m < 8; m++)
                out[r * HH + c0 + 16 * m] =
                    S_h[(r0 + i) * NPAD + c0 + 16 * m] + red2(acc[i][m]);
        }
    }

    if (tid < NTILE) {
        int r = n0 + tid;
        if (r < NN) {
            const float inv = 1.0f / (float)(NN - 1);
            out[NN * HH + r * 3 + 0] = x[r * 3 + 0] + g_xupd[r * 3 + 0] * inv;
            out[NN * HH + r * 3 + 1] = x[r * 3 + 1] + g_xupd[r * 3 + 1] * inv;
            out[NN * HH + r * 3 + 2] = x[r * 3 + 2] + g_xupd[r * 3 + 2] * inv;
        }
    }
}

// ---------------------------------------------------------------------------

extern "C" void kernel_launch(void* const* d_in, const int* in_sizes, int n_in,
                              void* d_out, int out_size) {
    const float* h   = (const float*)d_in[0];
    const float* x   = (const float*)d_in[1];
    const void*  ei  = d_in[2];
    const float* ew1 = (const float*)d_in[3];
    const float* eb1 = (const float*)d_in[4];
    const float* ew2 = (const float*)d_in[5];
    const float* eb2 = (const float*)d_in[6];
    const float* nw1 = (const float*)d_in[7];
    const float* nb1 = (const float*)d_in[8];
    const float* nw2 = (const float*)d_in[9];
    const float* nb2 = (const float*)d_in[10];
    const float* cw1 = (const float*)d_in[11];
    const float* cb1 = (const float*)d_in[12];
    const float* cw2 = (const float*)d_in[13];
    float* out = (float*)d_out;

    const int smem_node = (3 * NTILE * NPAD) * 4 + 8 * HH * 8;

    cudaFuncSetAttribute(edge_kernel, cudaFuncAttributeMaxDynamicSharedMemorySize, SMEM_EDGE);
    cudaFuncSetAttribute(node_kernel, cudaFuncAttributeMaxDynamicSharedMemorySize, smem_node);

    const int total = NN * HH + NN * 3;
    prep_kernel<<<(total + 255) / 256, 256>>>(ei, ew1, ew2, cw1);
    edge_kernel<<<EE / MT, ETHR, SMEM_EDGE>>>(h, x, ei, ew1, eb1, eb2, cb1, cw2);
    node_kernel<<<(NN + NTILE - 1) / NTILE, NTHR, smem_node>>>(h, x, nw1, nb1,
                                                               nw2, nb2, out);
}

// round 17
// speedup vs baseline: 1.4856x; 1.1727x over previous
#include <cuda_runtime.h>
#include <cuda_fp16.h>

#define NN   20000
#define EE   640000
#define HH   128
#define MT   128            // edges per tile (MMA M)
#define ETHR 256            // 8 warps: 4 row-groups x 2 col-halves (32x64)

#define NTILE 64            // node kernel tile
#define NPAD  132
#define NTHR  256

typedef unsigned int u32;
typedef unsigned long long u64;

// Padded fp16 row length (136*2=272B -> ldmatrix conflict-free phases)
#define KP   136
#define IMG  (128 * KP)            // one [128][136] fp16 image (elements)
#define STAGE_BYTES (IMG * 2)      // 34816 B per weight stage

// ---------------- device scratch (allocation-free rule) ----------------
__device__ __align__(16) float g_m_i[NN * HH];
__device__ __align__(16) float g_xupd[NN * 3];
__device__ int g_is64;
// 4 weight stages (W1a, W1b, W2, W3), each one [128][136] fp16 image [n][k]
__device__ __align__(16) __half g_wb[4 * IMG];

// silu via single-MUFU tanh.approx: v*sigmoid(v) = 0.5*v*(1 + tanh(v/2))
__device__ __forceinline__ float silu_f(float v) {
    float t;
    asm("tanh.approx.f32 %0, %1;" : "=f"(t) : "f"(0.5f * v));
    return 0.5f * v * (1.0f + t);
}

// ---------------- mma.sync helpers (baseline ISA) ----------------
__device__ __forceinline__ u32 smem_u32(const void* p) {
    u32 a;
    asm("{ .reg .u64 t; cvta.to.shared.u64 t, %1; cvt.u32.u64 %0, t; }"
        : "=r"(a) : "l"(p));
    return a;
}
__device__ __forceinline__ void ldm4(u32* r, u32 addr) {
    asm volatile("ldmatrix.sync.aligned.m8n8.x4.shared.b16 {%0,%1,%2,%3}, [%4];"
                 : "=r"(r[0]), "=r"(r[1]), "=r"(r[2]), "=r"(r[3]) : "r"(addr));
}
__device__ __forceinline__ void mma_f16(float* c, const u32* a, u32 b0, u32 b1) {
    asm volatile(
        "mma.sync.aligned.m16n8k16.row.col.f32.f16.f16.f32 "
        "{%0,%1,%2,%3}, {%4,%5,%6,%7}, {%8,%9}, {%0,%1,%2,%3};"
        : "+f"(c[0]), "+f"(c[1]), "+f"(c[2]), "+f"(c[3])
        : "r"(a[0]), "r"(a[1]), "r"(a[2]), "r"(a[3]), "r"(b0), "r"(b1));
}
// store (a,b) as half2 into the activation image
__device__ __forceinline__ void store_act(char* A, int m, int n, float a, float b) {
    __half2 p = __floats2half2_rn(a, b);
    *(u32*)(A + (u32)(m * KP + n) * 2) = *(u32*)&p;
}

// cp.async weight staging: one 34816B stage image -> smem, one commit group
__device__ __forceinline__ void stage_w(u32 dst, const __half* src, int tid) {
    const char* g = (const char*)src;
#pragma unroll
    for (int i = 0; i < 9; i++) {
        int idx = tid + i * ETHR;           // need 0..2175
        if (idx < 2176)
            asm volatile("cp.async.cg.shared.global [%0], [%1], 16;"
                         :: "r"(dst + idx * 16), "l"(g + (size_t)idx * 16) : "memory");
    }
    asm volatile("cp.async.commit_group;" ::: "memory");
}
template <int N> __device__ __forceinline__ void cp_wait() {
    asm volatile("cp.async.wait_group %0;" :: "n"(N) : "memory");
}

// ---------------------------------------------------------------------------
// Kernel 0: zero accumulators, detect index width, bake fp16 weight images
// [n][k] padded to KP (B^T, k contiguous) for ldmatrix.
// ---------------------------------------------------------------------------
__global__ void prep_kernel(const void* ei, const float* ew1,
                            const float* ew2, const float* cw1) {
    int i = blockIdx.x * blockDim.x + threadIdx.x;
    const int total = NN * HH + NN * 3;
    if (i < total) {
        if (i < NN * HH) g_m_i[i] = 0.0f;
        else             g_xupd[i - NN * HH] = 0.0f;
    }
    if (i < 65536) {
        int s = i >> 14, r = i & 16383;
        int k = r >> 7, n = r & 127;
        float v;
        if      (s == 0) v = ew1[k * 128 + n];
        else if (s == 1) v = ew1[(128 + k) * 128 + n];
        else if (s == 2) v = ew2[k * 128 + n];
        else             v = cw1[k * 128 + n];
        g_wb[(size_t)s * IMG + n * KP + k] = __float2half_rn(v);
    }
    if (blockIdx.x == 0 && threadIdx.x == 0) {
        const unsigned* w = (const unsigned*)ei;
        int is64 = 1;
        for (int kk = 0; kk < 32; kk++)
            if (w[2 * kk + 1] != 0u) { is64 = 0; break; }
        g_is64 = is64;
    }
}

// SMEM byte offsets (edge kernel): 2 weight buffers (dbuf) + A image + misc
#define OFF_W0   0
#define OFF_W1   STAGE_BYTES                 // 34816
#define OFF_A    (2 * STAGE_BYTES)           // 69632
#define OFF_MISC (3 * STAGE_BYTES)           // 104448
#define SMEM_EDGE (OFF_MISC + 6656)          // 111104  (2 CTAs/SM: 217 KB)

// One K=128 GEMM: warp-tile 32 rows x 64 cols, pure fp16.
// acc[16][4]: idx = rg*8 + 2t(+1); rg = row sub-group (+16 rows), t = n-tile.
// B fragments shared between the two row groups.
__device__ __forceinline__ void gemm_mma(float acc[16][4],
                                         u32 aImg, u32 wB,
                                         int lane, int wm, int nh)
{
    const int rA0 = wm * 32 + (lane & 15);
    const u32 aoff0 = (u32)(rA0 * KP + ((lane & 16) ? 8 : 0)) * 2;
    const u32 aoff1 = aoff0 + 16 * KP * 2;
    const int rB = nh * 64 + ((lane & 16) ? 8 : 0) + (lane & 7);
    const u32 boff = (u32)(rB * KP + ((lane & 8) ? 8 : 0)) * 2;

#pragma unroll
    for (int k0 = 0; k0 < 8; k0++) {
        u32 a0[4], a1[4];
        ldm4(a0, aImg + aoff0 + k0 * 32);
        ldm4(a1, aImg + aoff1 + k0 * 32);
#pragma unroll
        for (int t = 0; t < 4; t++) {
            u32 bh[4];
            ldm4(bh, wB + boff + (u32)t * (16 * KP * 2) + k0 * 32);
            mma_f16(acc[2 * t],         a0, bh[0], bh[1]);
            mma_f16(acc[2 * t + 1],     a0, bh[2], bh[3]);
            mma_f16(acc[8 + 2 * t],     a1, bh[0], bh[1]);
            mma_f16(acc[8 + 2 * t + 1], a1, bh[2], bh[3]);
        }
    }
}

// ---------------------------------------------------------------------------
// Kernel 1: fused edge pipeline (fp16 mma.sync, 2 CTAs/SM for overlap)
// ---------------------------------------------------------------------------
__global__ void __launch_bounds__(ETHR, 2) edge_kernel(
    const float* __restrict__ h, const float* __restrict__ x,
    const void* __restrict__ ei,
    const float* __restrict__ ew1,   // radial-row weights (fp32)
    const float* __restrict__ eb1, const float* __restrict__ eb2,
    const float* __restrict__ cb1, const float* __restrict__ cw2)
{
    extern __shared__ char smem[];
    char*  A_img = smem + OFF_A;
    float* s_eb1 = (float*)(smem + OFF_MISC);
    float* s_eb2 = s_eb1 + 128;
    float* s_cb1 = s_eb2 + 128;
    float* s_wl  = s_cb1 + 128;
    float* s_cw2 = s_wl + 128;
    float* s_rad = s_cw2 + 128;          // [128]
    float* s_cd  = s_rad + 128;          // [128][3]
    float* s_part = s_cd + 384;          // [128][2]
    int*   s_row = (int*)(s_part + 256); // [128]
    int*   s_col = s_row + 128;          // [128]

    const int tid  = threadIdx.x;
    const int lane = tid & 31;
    const int warp = tid >> 5;
    const int wm   = warp >> 1;          // 4 row groups of 32
    const int nh   = warp & 1;           // column half (64 cols)
    const int e0   = blockIdx.x * MT;

    const u32 sb  = smem_u32(smem);
    const u32 w0A = sb + OFF_W0, w1A = sb + OFF_W1;
    const u32 aA  = sb + OFF_A;

    // kick off W1a / W1b loads immediately (groups g0, g1)
    stage_w(w0A, g_wb,       tid);
    stage_w(w1A, g_wb + IMG, tid);

    // ---- per-tile metadata ----
    if (tid < MT) {
        int e = e0 + tid;
        int r, c;
        if (g_is64) {
            const long long* p = (const long long*)ei;
            r = (int)p[e]; c = (int)p[EE + e];
        } else {
            const int* p = (const int*)ei;
            r = p[e]; c = p[EE + e];
        }
        s_row[tid] = r; s_col[tid] = c;
        float dx = x[r * 3 + 0] - x[c * 3 + 0];
        float dy = x[r * 3 + 1] - x[c * 3 + 1];
        float dz = x[r * 3 + 2] - x[c * 3 + 2];
        s_cd[tid * 3 + 0] = dx; s_cd[tid * 3 + 1] = dy; s_cd[tid * 3 + 2] = dz;
        s_rad[tid] = dx * dx + dy * dy + dz * dz;
        s_eb1[tid] = eb1[tid];
        s_eb2[tid] = eb2[tid];
        s_cb1[tid] = cb1[tid];
        s_wl[tid]  = ew1[256 * 128 + tid];
        s_cw2[tid] = cw2[tid];
    }
    __syncthreads();                      // metadata visible

    const int l4 = lane >> 2, l2 = lane & 3;
    const int m00 = wm * 32 + l4, m01 = m00 + 8, m10 = m00 + 16, m11 = m00 + 24;

    float acc[16][4];
#pragma unroll
    for (int t = 0; t < 16; t++)
#pragma unroll
        for (int j = 0; j < 4; j++) acc[t][j] = 0.0f;

    // ---- gather h[row] -> A (each thread: one row half = 64 cols) ----
    {
        int r = tid >> 1, q = (tid & 1) * 64;
        const float4* hb = (const float4*)(h + (size_t)s_row[r] * HH + q);
#pragma unroll
        for (int i = 0; i < 16; i++) {
            float4 f = hb[i];
            int c = q + i * 4;
            store_act(A_img, r, c,     f.x, f.y);
            store_act(A_img, r, c + 2, f.z, f.w);
        }
    }
    cp_wait<1>();                         // g0 (W1a) landed
    __syncthreads();
    gemm_mma(acc, aA, w0A, lane, wm, nh);
    __syncthreads();

    // ---- prefetch W2 -> buf0; gather h[col] -> A ----
    stage_w(w0A, g_wb + 2 * IMG, tid);    // g2
    {
        int r = tid >> 1, q = (tid & 1) * 64;
        const float4* hb = (const float4*)(h + (size_t)s_col[r] * HH + q);
#pragma unroll
        for (int i = 0; i < 16; i++) {
            float4 f = hb[i];
            int c = q + i * 4;
            store_act(A_img, r, c,     f.x, f.y);
            store_act(A_img, r, c + 2, f.z, f.w);
        }
    }
    cp_wait<1>();                         // g1 (W1b) landed
    __syncthreads();
    gemm_mma(acc, aA, w1A, lane, wm, nh);
    __syncthreads();

    // ---- prefetch W3 -> buf1; epi1: t1 = silu(acc + eb1 + rad*wl) -> A ----
    stage_w(w1A, g_wb + 3 * IMG, tid);    // g3
    {
        float r0 = s_rad[m00], r1 = s_rad[m01], r2 = s_rad[m10], r3 = s_rad[m11];
#pragma unroll
        for (int rg = 0; rg < 2; rg++) {
            float ra = rg ? r2 : r0, rb = rg ? r3 : r1;
            int ma = rg ? m10 : m00, mb = rg ? m11 : m01;
#pragma unroll
            for (int nt = 0; nt < 8; nt++) {
                float* a = acc[rg * 8 + nt];
                int n = nh * 64 + nt * 8 + 2 * l2;
                float b0 = s_eb1[n], b1 = s_eb1[n + 1];
                float w0 = s_wl[n],  w1 = s_wl[n + 1];
                float v00 = silu_f(a[0] + b0 + ra * w0);
                float v01 = silu_f(a[1] + b1 + ra * w1);
                float v10 = silu_f(a[2] + b0 + rb * w0);
                float v11 = silu_f(a[3] + b1 + rb * w1);
                store_act(A_img, ma, n, v00, v01);
                store_act(A_img, mb, n, v10, v11);
                a[0] = a[1] = a[2] = a[3] = 0.0f;
            }
        }
    }
    cp_wait<1>();                         // g2 (W2) landed
    __syncthreads();
    gemm_mma(acc, aA, w0A, lane, wm, nh);
    __syncthreads();

    // ---- epi2: m_ij = silu(acc + eb2); m_i atomics; -> A ----
    {
        float* g0p = g_m_i + (size_t)s_row[m00] * HH;
        float* g1p = g_m_i + (size_t)s_row[m01] * HH;
        float* g2p = g_m_i + (size_t)s_row[m10] * HH;
        float* g3p = g_m_i + (size_t)s_row[m11] * HH;
#pragma unroll
        for (int rg = 0; rg < 2; rg++) {
            int ma = rg ? m10 : m00, mb = rg ? m11 : m01;
            float* ga = rg ? g2p : g0p;
            float* gb = rg ? g3p : g1p;
#pragma unroll
            for (int nt = 0; nt < 8; nt++) {
                float* a = acc[rg * 8 + nt];
                int n = nh * 64 + nt * 8 + 2 * l2;
                float b0 = s_eb2[n], b1 = s_eb2[n + 1];
                float v00 = silu_f(a[0] + b0);
                float v01 = silu_f(a[1] + b1);
                float v10 = silu_f(a[2] + b0);
                float v11 = silu_f(a[3] + b1);
                atomicAdd(ga + n,     v00);
                atomicAdd(ga + n + 1, v01);
                atomicAdd(gb + n,     v10);
                atomicAdd(gb + n + 1, v11);
                store_act(A_img, ma, n, v00, v01);
                store_act(A_img, mb, n, v10, v11);
                a[0] = a[1] = a[2] = a[3] = 0.0f;
            }
        }
    }
    cp_wait<0>();                         // g3 (W3) landed
    __syncthreads();
    gemm_mma(acc, aA, w1A, lane, wm, nh);

    // ---- epi3: coord_weight = silu(acc + cb1) . cw2 ----
    {
#pragma unroll
        for (int rg = 0; rg < 2; rg++) {
            float p0 = 0.0f, p1 = 0.0f;
#pragma unroll
            for (int nt = 0; nt < 8; nt++) {
                float* a = acc[rg * 8 + nt];
                int n = nh * 64 + nt * 8 + 2 * l2;
                float b0 = s_cb1[n], b1 = s_cb1[n + 1];
                float c0 = s_cw2[n], c1 = s_cw2[n + 1];
                p0 += silu_f(a[0] + b0) * c0 + silu_f(a[1] + b1) * c1;
                p1 += silu_f(a[2] + b0) * c0 + silu_f(a[3] + b1) * c1;
            }
            p0 += __shfl_xor_sync(0xffffffffu, p0, 1);
            p0 += __shfl_xor_sync(0xffffffffu, p0, 2);
            p1 += __shfl_xor_sync(0xffffffffu, p1, 1);
            p1 += __shfl_xor_sync(0xffffffffu, p1, 2);
            if (l2 == 0) {
                int ma = rg ? m10 : m00, mb = rg ? m11 : m01;
                s_part[ma * 2 + nh] = p0;
                s_part[mb * 2 + nh] = p1;
            }
        }
    }
    __syncthreads();

    if (tid < MT) {
        float w = s_part[tid * 2] + s_part[tid * 2 + 1];
        int r = s_row[tid];
        atomicAdd(&g_xupd[r * 3 + 0], s_cd[tid * 3 + 0] * w);
        atomicAdd(&g_xupd[r * 3 + 1], s_cd[tid * 3 + 1] * w);
        atomicAdd(&g_xupd[r * 3 + 2], s_cd[tid * 3 + 2] * w);
    }
}

// ---------------------------------------------------------------------------
// Kernel 2: node MLP + residual + x epilogue (SIMT f32x2 — small workload)
// ---------------------------------------------------------------------------
__device__ __forceinline__ void fma2(u64& d, u64 a, u64 b) {
    asm("fma.rn.f32x2 %0, %1, %2, %0;" : "+l"(d) : "l"(a), "l"(b));
}
__device__ __forceinline__ float red2(u64 v) {
    return __uint_as_float((unsigned)v) + __uint_as_float((unsigned)(v >> 32));
}

__device__ __forceinline__ void gemm2(u64 acc[4][8],
                                      const float* __restrict__ W,
                                      const float* __restrict__ Sin,
                                      float2* __restrict__ wbuf2,
                                      int tid, int r0, int c0)
{
#pragma unroll 1
    for (int k0 = 0; k0 < 128; k0 += 16) {
        __syncthreads();
#pragma unroll
        for (int t = 0; t < 4; t++) {
            int idx = tid + t * 256;
            int k2 = idx >> 7, j = idx & 127;
            wbuf2[idx] = make_float2(W[(k0 + 2 * k2) * HH + j],
                                     W[(k0 + 2 * k2 + 1) * HH + j]);
        }
        __syncthreads();
#pragma unroll
        for (int k2 = 0; k2 < 8; k2++) {
            u64 bb[8], aa[4];
#pragma unroll
            for (int m = 0; m < 8; m++)
                bb[m] = *(const u64*)&wbuf2[k2 * 128 + c0 + 16 * m];
#pragma unroll
            for (int i = 0; i < 4; i++)
                aa[i] = *(const u64*)&Sin[(r0 + i) * NPAD + k0 + 2 * k2];
#pragma unroll
            for (int i = 0; i < 4; i++)
#pragma unroll
                for (int m = 0; m < 8; m++)
                    fma2(acc[i][m], aa[i], bb[m]);
        }
    }
}

__global__ void __launch_bounds__(NTHR, 2) node_kernel(
    const float* __restrict__ h, const float* __restrict__ x,
    const float* __restrict__ nw1, const float* __restrict__ nb1,
    const float* __restrict__ nw2, const float* __restrict__ nb2,
    float* __restrict__ out)
{
    extern __shared__ float smemf[];
    float*  S_h   = smemf;
    float*  S_m   = S_h + NTILE * NPAD;
    float*  S_act = S_m + NTILE * NPAD;
    float2* wbuf2 = (float2*)(S_act + NTILE * NPAD);

    const int tid = threadIdx.x;
    const int n0  = blockIdx.x * NTILE;

    const float4* h4 = (const float4*)h;
    const float4* m4 = (const float4*)g_m_i;
    for (int i = tid; i < NTILE * 32; i += NTHR) {
        int rl = i >> 5, q = i & 31;
        int r = n0 + rl;
        float4 vh = make_float4(0.f, 0.f, 0.f, 0.f);
        float4 vm = vh;
        if (r < NN) { vh = h4[r * 32 + q]; vm = m4[r * 32 + q]; }
        *(float4*)&S_h[rl * NPAD + q * 4] = vh;
        *(float4*)&S_m[rl * NPAD + q * 4] = vm;
    }

    const int r0 = (tid >> 4) * 4;
    const int c0 = tid & 15;
    u64 acc[4][8];

#pragma unroll
    for (int m = 0; m < 8; m++) {
        float b = nb1[c0 + 16 * m];
#pragma unroll
        for (int i = 0; i < 4; i++) acc[i][m] = (u64)__float_as_uint(b);
    }
    gemm2(acc, nw1,            S_h, wbuf2, tid, r0, c0);
    gemm2(acc, nw1 + 128 * HH, S_m, wbuf2, tid, r0, c0);

#pragma unroll
    for (int i = 0; i < 4; i++)
#pragma unroll
        for (int m = 0; m < 8; m++)
            S_act[(r0 + i) * NPAD + c0 + 16 * m] = silu_f(red2(acc[i][m]));

#pragma unroll
    for (int m = 0; m < 8; m++) {
        float b = nb2[c0 + 16 * m];
#pragma unroll
        for (int i = 0; i < 4; i++) acc[i][m] = (u64)__float_as_uint(b);
    }
    gemm2(acc, nw2, S_act, wbuf2, tid, r0, c0);

#pragma unroll
    for (int i = 0; i < 4; i++) {
        int r = n0 + r0 + i;
        if (r < NN) {
#pragma unroll
            for (int m = 0; m < 8; m++)
                out[r * HH + c0 + 16 * m] =
                    S_h[(r0 + i) * NPAD + c0 + 16 * m] + red2(acc[i][m]);
        }
    }

    if (tid < NTILE) {
        int r = n0 + tid;
        if (r < NN) {
            const float inv = 1.0f / (float)(NN - 1);
            out[NN * HH + r * 3 + 0] = x[r * 3 + 0] + g_xupd[r * 3 + 0] * inv;
            out[NN * HH + r * 3 + 1] = x[r * 3 + 1] + g_xupd[r * 3 + 1] * inv;
            out[NN * HH + r * 3 + 2] = x[r * 3 + 2] + g_xupd[r * 3 + 2] * inv;
        }
    }
}

// ---------------------------------------------------------------------------

extern "C" void kernel_launch(void* const* d_in, const int* in_sizes, int n_in,
                              void* d_out, int out_size) {
    const float* h   = (const float*)d_in[0];
    const float* x   = (const float*)d_in[1];
    const void*  ei  = d_in[2];
    const float* ew1 = (const float*)d_in[3];
    const float* eb1 = (const float*)d_in[4];
    const float* ew2 = (const float*)d_in[5];
    const float* eb2 = (const float*)d_in[6];
    const float* nw1 = (const float*)d_in[7];
    const float* nb1 = (const float*)d_in[8];
    const float* nw2 = (const float*)d_in[9];
    const float* nb2 = (const float*)d_in[10];
    const float* cw1 = (const float*)d_in[11];
    const float* cb1 = (const float*)d_in[12];
    const float* cw2 = (const float*)d_in[13];
    float* out = (float*)d_out;

    const int smem_node = (3 * NTILE * NPAD) * 4 + 8 * HH * 8;

    cudaFuncSetAttribute(edge_kernel, cudaFuncAttributeMaxDynamicSharedMemorySize, SMEM_EDGE);
    cudaFuncSetAttribute(node_kernel, cudaFuncAttributeMaxDynamicSharedMemorySize, smem_node);

    const int total = NN * HH + NN * 3;
    prep_kernel<<<(total + 255) / 256, 256>>>(ei, ew1, ew2, cw1);
    edge_kernel<<<EE / MT, ETHR, SMEM_EDGE>>>(h, x, ei, ew1, eb1, eb2, cb1, cw2);
    node_kernel<<<(NN + NTILE - 1) / NTILE, NTHR, smem_node>>>(h, x, nw1, nb1,
                                                               nw2, nb2, out);
}